// round 10
// baseline (speedup 1.0000x reference)
#include <cuda_runtime.h>
#include <cuda_bf16.h>
#include <math.h>
#include <stdint.h>

#define N_NODES 10000
#define N_EDGES 640000
#define FDIM    128
#define N_TILES (N_EDGES / 128)   // 5000

#define LDA 264   // smem stride (bf16 elems) for A tile: 256 + 8
#define LDH 136   // smem stride for h tile: 128 + 8

// ---- smem map (bytes) ----
#define SM_ROW   0        // 128 ints
#define SM_B1    512      // 128 floats
#define SM_B2    1024     // 128 floats
#define SM_A     2048
#define SM_ALO   (SM_A + 128 * LDA * 2)        // +67584
#define SM_TOTAL (SM_ALO + 128 * LDA * 2)      // 137216
#define SM_HHI   SM_A                           // overlay after gemm1
#define SM_HLO   (SM_A + 128 * LDH * 2)

// ===========================================================================
// Global scratch (no cudaMalloc allowed)
// ===========================================================================
__device__ float g_agg[N_NODES * FDIM];
__device__ __nv_bfloat16 gFhi[N_NODES * FDIM];
__device__ __nv_bfloat16 gFlo[N_NODES * FDIM];
// weight fragments: index [frag_id][lane], frag_id = kstep*16 + nfrag
__device__ uint2 gW1hf[256 * 32];
__device__ uint2 gW1lf[256 * 32];
__device__ uint2 gW2hf[128 * 32];
__device__ uint2 gW2lf[128 * 32];

typedef unsigned long long u64;

__device__ __forceinline__ float sigmoidf_(float x) { return 1.0f / (1.0f + __expf(-x)); }
__device__ __forceinline__ float softsignf_(float x) { return x / (1.0f + fabsf(x)); }

__device__ __forceinline__ uint32_t smem_u32(const void* p) {
    uint32_t a;
    asm("{ .reg .u64 t; cvta.to.shared.u64 t, %1; cvt.u32.u64 %0, t; }" : "=r"(a) : "l"(p));
    return a;
}
__device__ __forceinline__ uint32_t pack_bf2(__nv_bfloat16 lo, __nv_bfloat16 hi) {
    __nv_bfloat162 v; v.x = lo; v.y = hi;
    return *(uint32_t*)&v;
}
__device__ __forceinline__ void mma_bf16(float4& d, const uint32_t a[4], uint2 b) {
    asm volatile(
        "mma.sync.aligned.m16n8k16.row.col.f32.bf16.bf16.f32 "
        "{%0,%1,%2,%3}, {%4,%5,%6,%7}, {%8,%9}, {%0,%1,%2,%3};"
        : "+f"(d.x), "+f"(d.y), "+f"(d.z), "+f"(d.w)
        : "r"(a[0]), "r"(a[1]), "r"(a[2]), "r"(a[3]), "r"(b.x), "r"(b.y));
}
__device__ __forceinline__ void ldmx4(uint32_t r[4], uint32_t addr) {
    asm volatile("ldmatrix.sync.aligned.m8n8.x4.shared.b16 {%0,%1,%2,%3}, [%4];"
                 : "=r"(r[0]), "=r"(r[1]), "=r"(r[2]), "=r"(r[3]) : "r"(addr));
}
__device__ __forceinline__ void red2(float* p, float v0, float v1) {
    asm volatile("red.global.add.v2.f32 [%0], {%1, %2};" :: "l"(p), "f"(v0), "f"(v1) : "memory");
}
// f32x2 helpers (node kernel, validated R7)
__device__ __forceinline__ void ffma2(u64& d, u64 a, u64 b) {
    asm("fma.rn.f32x2 %0, %1, %2, %0;" : "+l"(d) : "l"(a), "l"(b));
}
__device__ __forceinline__ u64 pack2(float s) {
    u64 r; asm("mov.b64 %0, {%1, %1};" : "=l"(r) : "f"(s)); return r;
}
__device__ __forceinline__ void unpack2(u64 v, float& lo, float& hi) {
    asm("mov.b64 {%0, %1}, %2;" : "=f"(lo), "=f"(hi) : "l"(v));
}
__device__ __forceinline__ void ldg2x2(const float* p, u64& d0, u64& d1) {
    asm("ld.global.nc.v2.b64 {%0, %1}, [%2];" : "=l"(d0), "=l"(d1) : "l"(p));
}

// ===========================================================================
// Prep kernels
// ===========================================================================
__global__ void prep_features(const float* __restrict__ f) {
    int i = blockIdx.x * 256 + threadIdx.x;
    if (i < N_NODES * FDIM) {
        float x = f[i];
        __nv_bfloat16 h = __float2bfloat16_rn(x);
        gFhi[i] = h;
        gFlo[i] = __float2bfloat16_rn(x - __bfloat162float(h));
    }
}
__global__ void prep_wfrag(const float* __restrict__ W, int ksteps,
                           uint2* __restrict__ outH, uint2* __restrict__ outL) {
    int i = blockIdx.x * 256 + threadIdx.x;
    if (i >= ksteps * 16 * 32) return;
    int lane = i & 31, fi = i >> 5;
    int kstep = fi >> 4, nfg = fi & 15;
    int n = nfg * 8 + (lane >> 2);
    __nv_bfloat16 hi[2][2], lo[2][2];
    #pragma unroll
    for (int j = 0; j < 2; j++)
        #pragma unroll
        for (int h = 0; h < 2; h++) {
            int k = kstep * 16 + j * 8 + (lane & 3) * 2 + h;
            float x = W[k * 128 + n];
            __nv_bfloat16 xh = __float2bfloat16_rn(x);
            hi[j][h] = xh;
            lo[j][h] = __float2bfloat16_rn(x - __bfloat162float(xh));
        }
    outH[i] = make_uint2(pack_bf2(hi[0][0], hi[0][1]), pack_bf2(hi[1][0], hi[1][1]));
    outL[i] = make_uint2(pack_bf2(lo[0][0], lo[0][1]), pack_bf2(lo[1][0], lo[1][1]));
}

// ===========================================================================
// Edge kernel: persistent, 148 CTAs x 512 threads (16 warps: 4M x 4N).
// Tile = 128 edges x 128 outputs. Split-bf16 mma.sync (3 terms).
// 16 warps -> 4 warps/SMSP for latency hiding (R9 had 2).
// ===========================================================================
__global__ void __launch_bounds__(512, 1)
edge_mma_kernel(const int* __restrict__ rows,
                const int* __restrict__ cols,
                const float* __restrict__ bm1,
                const float* __restrict__ bm2)
{
    extern __shared__ char smem[];
    int*   sRow = (int*)(smem + SM_ROW);
    float* sB1  = (float*)(smem + SM_B1);
    float* sB2  = (float*)(smem + SM_B2);
    __nv_bfloat16* sAhi = (__nv_bfloat16*)(smem + SM_A);
    __nv_bfloat16* sAlo = (__nv_bfloat16*)(smem + SM_ALO);
    __nv_bfloat16* sHhi = (__nv_bfloat16*)(smem + SM_HHI);
    __nv_bfloat16* sHlo = (__nv_bfloat16*)(smem + SM_HLO);

    const int tid  = threadIdx.x;
    const int lane = tid & 31;
    const int wid  = tid >> 5;
    const int wm   = wid & 3;   // M quadrant: rows [wm*32, wm*32+32)
    const int wn   = wid >> 2;  // N quadrant: cols [wn*32, wn*32+32)
    const uint32_t sb = smem_u32(smem);

    if (tid < 128) { sB1[tid] = __ldg(bm1 + tid); sB2[tid] = __ldg(bm2 + tid); }

    const int arow  = lane & 15;
    const int acolk = (lane >> 4) * 8;
    const int erow  = lane >> 2;           // + m*16 (+8 for .z/.w)
    const int ecol  = (lane & 3) * 2;      // + nf*8 + wn*32

    for (int t = blockIdx.x; t < N_TILES; t += gridDim.x) {
        const int e0 = t * 128;

        // ---- gather split features into smem A (512 threads, 1 row each) ----
        if (tid < 128) sRow[tid] = __ldg(rows + e0 + tid);
        {
            int e = tid >> 2, part = tid & 3;     // part: bit0 = src/dst, bit1 = hi/lo
            int node = (part & 1) ? __ldg(cols + e0 + e) : __ldg(rows + e0 + e);
            const uint4* src = (const uint4*)(((part & 2) ? gFlo : gFhi) + (size_t)node * FDIM);
            uint4* dst = (uint4*)(((part & 2) ? sAlo : sAhi) + e * LDA + (part & 1) * FDIM);
            #pragma unroll
            for (int i = 0; i < 16; i++) dst[i] = __ldg(src + i);
        }
        __syncthreads();

        // ---- GEMM1: [128,256] @ W1[256,128], 3-term split bf16 ----
        float4 acc[2][4];
        #pragma unroll
        for (int m = 0; m < 2; m++)
            #pragma unroll
            for (int nf = 0; nf < 4; nf++) acc[m][nf] = make_float4(0.f, 0.f, 0.f, 0.f);

        #pragma unroll 1
        for (int ks = 0; ks < 16; ks++) {
            uint32_t ah[2][4], al[2][4];
            #pragma unroll
            for (int m = 0; m < 2; m++) {
                uint32_t ab = sb + SM_A +
                    (uint32_t)(((wm * 32 + m * 16 + arow) * LDA + ks * 16 + acolk) * 2);
                ldmx4(ah[m], ab);
                ldmx4(al[m], ab + 128 * LDA * 2);
            }
            #pragma unroll
            for (int nf = 0; nf < 4; nf++) {
                int fi = ks * 16 + wn * 4 + nf;
                uint2 bh = __ldg(&gW1hf[fi * 32 + lane]);
                uint2 bl = __ldg(&gW1lf[fi * 32 + lane]);
                #pragma unroll
                for (int m = 0; m < 2; m++) {
                    mma_bf16(acc[m][nf], ah[m], bh);
                    mma_bf16(acc[m][nf], ah[m], bl);
                    mma_bf16(acc[m][nf], al[m], bh);
                }
            }
        }
        __syncthreads();   // all warps done reading sA before sH overlay

        // ---- epilogue 1: h = sigmoid(D1 + bm1) -> split bf16 -> smem ----
        #pragma unroll
        for (int m = 0; m < 2; m++)
            #pragma unroll
            for (int nf = 0; nf < 4; nf++) {
                int r0 = wm * 32 + m * 16 + erow;
                int c  = wn * 32 + nf * 8 + ecol;
                float b0 = sB1[c], b1 = sB1[c + 1];
                float f0 = sigmoidf_(acc[m][nf].x + b0);
                float f1 = sigmoidf_(acc[m][nf].y + b1);
                float f2 = sigmoidf_(acc[m][nf].z + b0);
                float f3 = sigmoidf_(acc[m][nf].w + b1);
                __nv_bfloat16 h0 = __float2bfloat16_rn(f0), h1 = __float2bfloat16_rn(f1);
                __nv_bfloat16 h2 = __float2bfloat16_rn(f2), h3 = __float2bfloat16_rn(f3);
                *(uint32_t*)(sHhi + r0 * LDH + c)       = pack_bf2(h0, h1);
                *(uint32_t*)(sHhi + (r0 + 8) * LDH + c) = pack_bf2(h2, h3);
                *(uint32_t*)(sHlo + r0 * LDH + c) =
                    pack_bf2(__float2bfloat16_rn(f0 - __bfloat162float(h0)),
                             __float2bfloat16_rn(f1 - __bfloat162float(h1)));
                *(uint32_t*)(sHlo + (r0 + 8) * LDH + c) =
                    pack_bf2(__float2bfloat16_rn(f2 - __bfloat162float(h2)),
                             __float2bfloat16_rn(f3 - __bfloat162float(h3)));
            }
        __syncthreads();

        // ---- GEMM2: [128,128] @ W2[128,128] ----
        float4 acc2[2][4];
        #pragma unroll
        for (int m = 0; m < 2; m++)
            #pragma unroll
            for (int nf = 0; nf < 4; nf++) acc2[m][nf] = make_float4(0.f, 0.f, 0.f, 0.f);

        #pragma unroll 1
        for (int ks = 0; ks < 8; ks++) {
            uint32_t ah[2][4], al[2][4];
            #pragma unroll
            for (int m = 0; m < 2; m++) {
                uint32_t ab = sb + SM_HHI +
                    (uint32_t)(((wm * 32 + m * 16 + arow) * LDH + ks * 16 + acolk) * 2);
                ldmx4(ah[m], ab);
                ldmx4(al[m], ab + (SM_HLO - SM_HHI));
            }
            #pragma unroll
            for (int nf = 0; nf < 4; nf++) {
                int fi = ks * 16 + wn * 4 + nf;
                uint2 bh = __ldg(&gW2hf[fi * 32 + lane]);
                uint2 bl = __ldg(&gW2lf[fi * 32 + lane]);
                #pragma unroll
                for (int m = 0; m < 2; m++) {
                    mma_bf16(acc2[m][nf], ah[m], bh);
                    mma_bf16(acc2[m][nf], ah[m], bl);
                    mma_bf16(acc2[m][nf], al[m], bh);
                }
            }
        }

        // ---- epilogue 2: softsign + red scatter into g_agg ----
        #pragma unroll
        for (int m = 0; m < 2; m++) {
            int r0 = wm * 32 + m * 16 + erow;
            int n0 = sRow[r0];
            int n1 = sRow[r0 + 8];
            #pragma unroll
            for (int nf = 0; nf < 4; nf++) {
                int c = wn * 32 + nf * 8 + ecol;
                float b0 = sB2[c], b1 = sB2[c + 1];
                red2(g_agg + (size_t)n0 * FDIM + c,
                     softsignf_(acc2[m][nf].x + b0), softsignf_(acc2[m][nf].y + b1));
                red2(g_agg + (size_t)n1 * FDIM + c,
                     softsignf_(acc2[m][nf].z + b0), softsignf_(acc2[m][nf].w + b1));
            }
        }
        __syncthreads();   // before next tile's gather overwrites sA/sRow
    }
}

// ===========================================================================
// Node kernel (R7 version, unchanged)
// ===========================================================================
#define TEN 64
#define NLDH 132
#define NLDN 388

__global__ void __launch_bounds__(256, 2)
node_kernel(const float* __restrict__ features,
            const float* __restrict__ time_emb,
            const float* __restrict__ Wf1,
            const float* __restrict__ bf1,
            const float* __restrict__ Wf2,
            const float* __restrict__ bf2,
            float* __restrict__ out)
{
    extern __shared__ float smemf[];
    float* sIn = smemf;

    const int tid = threadIdx.x;
    const int tx  = tid & 31;
    const int ty  = tid >> 5;
    const int n0  = blockIdx.x * TEN;

    for (int n = ty; n < TEN; n += 8) {
        int node = n0 + n;
        float4 a, g, t;
        if (node < N_NODES) {
            a = __ldg((const float4*)(features + (size_t)node * FDIM) + tx);
            g = *((const float4*)(g_agg + (size_t)node * FDIM) + tx);
            t = __ldg((const float4*)(time_emb + (size_t)node * FDIM) + tx);
        } else {
            a = g = t = make_float4(0.f, 0.f, 0.f, 0.f);
        }
        *(float4*)&sIn[n * NLDN + tx * 4] =
            make_float4(sigmoidf_(a.x), sigmoidf_(a.y), sigmoidf_(a.z), sigmoidf_(a.w));
        *(float4*)&sIn[n * NLDN + FDIM + tx * 4] =
            make_float4(sigmoidf_(g.x), sigmoidf_(g.y), sigmoidf_(g.z), sigmoidf_(g.w));
        *(float4*)&sIn[n * NLDN + 2 * FDIM + tx * 4] =
            make_float4(sigmoidf_(t.x), sigmoidf_(t.y), sigmoidf_(t.z), sigmoidf_(t.w));
    }
    __syncthreads();

    u64 acc[8][2];
    #pragma unroll
    for (int e = 0; e < 8; e++) { acc[e][0] = 0ull; acc[e][1] = 0ull; }

    const float* wBase = Wf1 + tx * 4;
    const float* aBase = sIn + (ty * 8) * NLDN;

    #pragma unroll 2
    for (int k = 0; k < 3 * FDIM; k += 4) {
        u64 w0a, w0b, w1a, w1b, w2a, w2b, w3a, w3b;
        ldg2x2(wBase + (k + 0) * FDIM, w0a, w0b);
        ldg2x2(wBase + (k + 1) * FDIM, w1a, w1b);
        ldg2x2(wBase + (k + 2) * FDIM, w2a, w2b);
        ldg2x2(wBase + (k + 3) * FDIM, w3a, w3b);
        #pragma unroll
        for (int e = 0; e < 8; e++) {
            float4 a = *(const float4*)(aBase + e * NLDN + k);
            u64 a0 = pack2(a.x), a1 = pack2(a.y), a2 = pack2(a.z), a3 = pack2(a.w);
            ffma2(acc[e][0], a0, w0a); ffma2(acc[e][1], a0, w0b);
            ffma2(acc[e][0], a1, w1a); ffma2(acc[e][1], a1, w1b);
            ffma2(acc[e][0], a2, w2a); ffma2(acc[e][1], a2, w2b);
            ffma2(acc[e][0], a3, w3a); ffma2(acc[e][1], a3, w3b);
        }
    }
    __syncthreads();

    float4 b1 = __ldg((const float4*)bf1 + tx);
    float* sH = smemf;
    #pragma unroll
    for (int e = 0; e < 8; e++) {
        float x0, x1, x2, x3;
        unpack2(acc[e][0], x0, x1);
        unpack2(acc[e][1], x2, x3);
        float4 h;
        h.x = sigmoidf_(x0 + b1.x);
        h.y = sigmoidf_(x1 + b1.y);
        h.z = sigmoidf_(x2 + b1.z);
        h.w = sigmoidf_(x3 + b1.w);
        *(float4*)&sH[(ty * 8 + e) * NLDH + tx * 4] = h;
    }
    __syncthreads();

    u64 acc2[8][2];
    #pragma unroll
    for (int e = 0; e < 8; e++) { acc2[e][0] = 0ull; acc2[e][1] = 0ull; }

    const float* w2Base = Wf2 + tx * 4;
    const float* hBase  = sH + (ty * 8) * NLDH;

    #pragma unroll 2
    for (int k = 0; k < FDIM; k += 4) {
        u64 w0a, w0b, w1a, w1b, w2a, w2b, w3a, w3b;
        ldg2x2(w2Base + (k + 0) * FDIM, w0a, w0b);
        ldg2x2(w2Base + (k + 1) * FDIM, w1a, w1b);
        ldg2x2(w2Base + (k + 2) * FDIM, w2a, w2b);
        ldg2x2(w2Base + (k + 3) * FDIM, w3a, w3b);
        #pragma unroll
        for (int e = 0; e < 8; e++) {
            float4 a = *(const float4*)(hBase + e * NLDH + k);
            u64 a0 = pack2(a.x), a1 = pack2(a.y), a2 = pack2(a.z), a3 = pack2(a.w);
            ffma2(acc2[e][0], a0, w0a); ffma2(acc2[e][1], a0, w0b);
            ffma2(acc2[e][0], a1, w1a); ffma2(acc2[e][1], a1, w1b);
            ffma2(acc2[e][0], a2, w2a); ffma2(acc2[e][1], a2, w2b);
            ffma2(acc2[e][0], a3, w3a); ffma2(acc2[e][1], a3, w3b);
        }
    }

    float4 b2 = __ldg((const float4*)bf2 + tx);
    #pragma unroll
    for (int e = 0; e < 8; e++) {
        int node = n0 + ty * 8 + e;
        if (node < N_NODES) {
            float x0, x1, x2, x3;
            unpack2(acc2[e][0], x0, x1);
            unpack2(acc2[e][1], x2, x3);
            float4 o;
            o.x = softsignf_(x0 + b2.x);
            o.y = softsignf_(x1 + b2.y);
            o.z = softsignf_(x2 + b2.z);
            o.w = softsignf_(x3 + b2.w);
            *(float4*)(out + (size_t)node * FDIM + tx * 4) = o;
        }
    }
}

// ===========================================================================
extern "C" void kernel_launch(void* const* d_in, const int* in_sizes, int n_in,
                              void* d_out, int out_size)
{
    const float* features = (const float*)d_in[0];
    const int*   rows     = (const int*)  d_in[1];
    const int*   cols     = (const int*)  d_in[2];
    const float* time_emb = (const float*)d_in[3];
    const float* Wm1      = (const float*)d_in[4];
    const float* bm1      = (const float*)d_in[5];
    const float* Wm2      = (const float*)d_in[6];
    const float* bm2      = (const float*)d_in[7];
    const float* Wf1      = (const float*)d_in[8];
    const float* bf1      = (const float*)d_in[9];
    const float* Wf2      = (const float*)d_in[10];
    const float* bf2      = (const float*)d_in[11];
    float* out = (float*)d_out;

    const int node_smem = TEN * NLDN * sizeof(float);
    cudaFuncSetAttribute(edge_mma_kernel, cudaFuncAttributeMaxDynamicSharedMemorySize, SM_TOTAL);
    cudaFuncSetAttribute(node_kernel,     cudaFuncAttributeMaxDynamicSharedMemorySize, node_smem);

    void* aggp = nullptr;
    cudaGetSymbolAddress(&aggp, g_agg);
    cudaMemsetAsync(aggp, 0, (size_t)N_NODES * FDIM * sizeof(float));

    uint2 *w1h, *w1l, *w2h, *w2l;
    cudaGetSymbolAddress((void**)&w1h, gW1hf);
    cudaGetSymbolAddress((void**)&w1l, gW1lf);
    cudaGetSymbolAddress((void**)&w2h, gW2hf);
    cudaGetSymbolAddress((void**)&w2l, gW2lf);

    prep_features<<<(N_NODES * FDIM + 255) / 256, 256>>>(features);
    prep_wfrag<<<32, 256>>>(Wm1, 16, w1h, w1l);
    prep_wfrag<<<16, 256>>>(Wm2,  8, w2h, w2l);

    edge_mma_kernel<<<148, 512, SM_TOTAL>>>(rows, cols, bm1, bm2);

    node_kernel<<<(N_NODES + TEN - 1) / TEN, 256, node_smem>>>(features, time_emb,
                                                               Wf1, bf1, Wf2, bf2, out);
}

// round 11
// speedup vs baseline: 1.0727x; 1.0727x over previous
#include <cuda_runtime.h>
#include <cuda_bf16.h>
#include <math.h>
#include <stdint.h>

#define N_NODES 10000
#define N_EDGES 640000
#define FDIM    128
#define TILE_E  64
#define N_TILES (N_EDGES / TILE_E)   // 10000

#define LDA 264   // smem stride (bf16) for A tile: 256 + 8  (row stride 33x16B -> ldmatrix conflict-free)
#define LDH 136   // smem stride (bf16) for h tile: 128 + 8  (17x16B -> conflict-free)

// ---- smem map (bytes), per CTA ~104KB -> 2 CTAs/SM ----
#define SM_ROW   0                                   // 64 ints
#define SM_B1    256                                  // 128 floats
#define SM_B2    768                                  // 128 floats
#define SM_A     1280
#define SM_ALO   (SM_A   + TILE_E * LDA * 2)          // +33792
#define SM_HHI   (SM_ALO + TILE_E * LDA * 2)          // separate H (no overlay)
#define SM_HLO   (SM_HHI + TILE_E * LDH * 2)
#define SM_TOTAL (SM_HLO + TILE_E * LDH * 2)          // 103680

// ===========================================================================
// Global scratch (no cudaMalloc allowed)
// ===========================================================================
__device__ float g_agg[N_NODES * FDIM];
__device__ __nv_bfloat16 gFhi[N_NODES * FDIM];
__device__ __nv_bfloat16 gFlo[N_NODES * FDIM];
// weight fragments: index [frag_id][lane], frag_id = kstep*16 + nfrag
__device__ uint2 gW1hf[256 * 32];
__device__ uint2 gW1lf[256 * 32];
__device__ uint2 gW2hf[128 * 32];
__device__ uint2 gW2lf[128 * 32];

typedef unsigned long long u64;

__device__ __forceinline__ float sigmoidf_(float x) { return 1.0f / (1.0f + __expf(-x)); }
__device__ __forceinline__ float softsignf_(float x) { return x / (1.0f + fabsf(x)); }

__device__ __forceinline__ uint32_t smem_u32(const void* p) {
    uint32_t a;
    asm("{ .reg .u64 t; cvta.to.shared.u64 t, %1; cvt.u32.u64 %0, t; }" : "=r"(a) : "l"(p));
    return a;
}
__device__ __forceinline__ uint32_t pack_bf2(__nv_bfloat16 lo, __nv_bfloat16 hi) {
    __nv_bfloat162 v; v.x = lo; v.y = hi;
    return *(uint32_t*)&v;
}
__device__ __forceinline__ void mma_bf16(float4& d, const uint32_t a[4], uint2 b) {
    asm volatile(
        "mma.sync.aligned.m16n8k16.row.col.f32.bf16.bf16.f32 "
        "{%0,%1,%2,%3}, {%4,%5,%6,%7}, {%8,%9}, {%0,%1,%2,%3};"
        : "+f"(d.x), "+f"(d.y), "+f"(d.z), "+f"(d.w)
        : "r"(a[0]), "r"(a[1]), "r"(a[2]), "r"(a[3]), "r"(b.x), "r"(b.y));
}
__device__ __forceinline__ void ldmx4(uint32_t r[4], uint32_t addr) {
    asm volatile("ldmatrix.sync.aligned.m8n8.x4.shared.b16 {%0,%1,%2,%3}, [%4];"
                 : "=r"(r[0]), "=r"(r[1]), "=r"(r[2]), "=r"(r[3]) : "r"(addr));
}
__device__ __forceinline__ void red2(float* p, float v0, float v1) {
    asm volatile("red.global.add.v2.f32 [%0], {%1, %2};" :: "l"(p), "f"(v0), "f"(v1) : "memory");
}
// f32x2 helpers (node kernel, validated R7)
__device__ __forceinline__ void ffma2(u64& d, u64 a, u64 b) {
    asm("fma.rn.f32x2 %0, %1, %2, %0;" : "+l"(d) : "l"(a), "l"(b));
}
__device__ __forceinline__ u64 pack2(float s) {
    u64 r; asm("mov.b64 %0, {%1, %1};" : "=l"(r) : "f"(s)); return r;
}
__device__ __forceinline__ void unpack2(u64 v, float& lo, float& hi) {
    asm("mov.b64 {%0, %1}, %2;" : "=f"(lo), "=f"(hi) : "l"(v));
}
__device__ __forceinline__ void ldg2x2(const float* p, u64& d0, u64& d1) {
    asm("ld.global.nc.v2.b64 {%0, %1}, [%2];" : "=l"(d0), "=l"(d1) : "l"(p));
}

// ===========================================================================
// Prep kernels
// ===========================================================================
__global__ void prep_features(const float* __restrict__ f) {
    int i = blockIdx.x * 256 + threadIdx.x;
    if (i < N_NODES * FDIM) {
        float x = f[i];
        __nv_bfloat16 h = __float2bfloat16_rn(x);
        gFhi[i] = h;
        gFlo[i] = __float2bfloat16_rn(x - __bfloat162float(h));
    }
}
__global__ void prep_wfrag(const float* __restrict__ W, int ksteps,
                           uint2* __restrict__ outH, uint2* __restrict__ outL) {
    int i = blockIdx.x * 256 + threadIdx.x;
    if (i >= ksteps * 16 * 32) return;
    int lane = i & 31, fi = i >> 5;
    int kstep = fi >> 4, nfg = fi & 15;
    int n = nfg * 8 + (lane >> 2);
    __nv_bfloat16 hi[2][2], lo[2][2];
    #pragma unroll
    for (int j = 0; j < 2; j++)
        #pragma unroll
        for (int h = 0; h < 2; h++) {
            int k = kstep * 16 + j * 8 + (lane & 3) * 2 + h;
            float x = W[k * 128 + n];
            __nv_bfloat16 xh = __float2bfloat16_rn(x);
            hi[j][h] = xh;
            lo[j][h] = __float2bfloat16_rn(x - __bfloat162float(xh));
        }
    outH[i] = make_uint2(pack_bf2(hi[0][0], hi[0][1]), pack_bf2(hi[1][0], hi[1][1]));
    outL[i] = make_uint2(pack_bf2(lo[0][0], lo[0][1]), pack_bf2(lo[1][0], lo[1][1]));
}

// ===========================================================================
// Edge kernel: persistent, 296 CTAs x 256 threads, 2 CTAs/SM for phase overlap.
// Tile = 64 edges x 128 outputs, 8 warps = 2M x 4N. Split-bf16 mma.sync.
// 3 __syncthreads per tile (H is separate, not overlaid).
// ===========================================================================
__global__ void __launch_bounds__(256, 2)
edge_mma_kernel(const int* __restrict__ rows,
                const int* __restrict__ cols,
                const float* __restrict__ bm1,
                const float* __restrict__ bm2)
{
    extern __shared__ char smem[];
    int*   sRow = (int*)(smem + SM_ROW);
    float* sB1  = (float*)(smem + SM_B1);
    float* sB2  = (float*)(smem + SM_B2);
    __nv_bfloat16* sAhi = (__nv_bfloat16*)(smem + SM_A);
    __nv_bfloat16* sAlo = (__nv_bfloat16*)(smem + SM_ALO);
    __nv_bfloat16* sHhi = (__nv_bfloat16*)(smem + SM_HHI);
    __nv_bfloat16* sHlo = (__nv_bfloat16*)(smem + SM_HLO);

    const int tid  = threadIdx.x;
    const int lane = tid & 31;
    const int wid  = tid >> 5;
    const int wm   = wid & 1;   // M half:     rows [wm*32, wm*32+32)
    const int wn   = wid >> 1;  // N quadrant: cols [wn*32, wn*32+32)
    const uint32_t sb = smem_u32(smem);

    if (tid < 128) { sB1[tid] = __ldg(bm1 + tid); sB2[tid] = __ldg(bm2 + tid); }

    const int arow  = lane & 15;
    const int acolk = (lane >> 4) * 8;
    const int erow  = lane >> 2;           // + m*16 (+8 for .z/.w)
    const int ecol  = (lane & 3) * 2;      // + nf*8 + wn*32

    for (int t = blockIdx.x; t < N_TILES; t += gridDim.x) {
        const int e0 = t * TILE_E;

        // ---- gather split features (64 edges x 4 parts = 256 threads) ----
        if (tid < TILE_E) sRow[tid] = __ldg(rows + e0 + tid);
        {
            int e = tid >> 2, part = tid & 3;     // bit0 = src/dst, bit1 = hi/lo
            int node = (part & 1) ? __ldg(cols + e0 + e) : __ldg(rows + e0 + e);
            const uint4* src = (const uint4*)(((part & 2) ? gFlo : gFhi) + (size_t)node * FDIM);
            uint4* dst = (uint4*)(((part & 2) ? sAlo : sAhi) + e * LDA + (part & 1) * FDIM);
            #pragma unroll
            for (int i = 0; i < 16; i++) dst[i] = __ldg(src + i);
        }
        __syncthreads();

        // ---- GEMM1: [64,256] @ W1[256,128], 3-term split bf16 ----
        float4 acc[2][4];
        #pragma unroll
        for (int m = 0; m < 2; m++)
            #pragma unroll
            for (int nf = 0; nf < 4; nf++) acc[m][nf] = make_float4(0.f, 0.f, 0.f, 0.f);

        #pragma unroll 1
        for (int ks = 0; ks < 16; ks++) {
            uint32_t ah[2][4], al[2][4];
            #pragma unroll
            for (int m = 0; m < 2; m++) {
                uint32_t ab = sb + SM_A +
                    (uint32_t)(((wm * 32 + m * 16 + arow) * LDA + ks * 16 + acolk) * 2);
                ldmx4(ah[m], ab);
                ldmx4(al[m], ab + (SM_ALO - SM_A));
            }
            #pragma unroll
            for (int nf = 0; nf < 4; nf++) {
                int fi = ks * 16 + wn * 4 + nf;
                uint2 bh = __ldg(&gW1hf[fi * 32 + lane]);
                uint2 bl = __ldg(&gW1lf[fi * 32 + lane]);
                #pragma unroll
                for (int m = 0; m < 2; m++) {
                    mma_bf16(acc[m][nf], ah[m], bh);
                    mma_bf16(acc[m][nf], ah[m], bl);
                    mma_bf16(acc[m][nf], al[m], bh);
                }
            }
        }

        // ---- epilogue 1: h = sigmoid(D1 + bm1) -> split bf16 -> separate sH ----
        // (no barrier needed before this: sH is not aliased with sA)
        #pragma unroll
        for (int m = 0; m < 2; m++)
            #pragma unroll
            for (int nf = 0; nf < 4; nf++) {
                int r0 = wm * 32 + m * 16 + erow;
                int c  = wn * 32 + nf * 8 + ecol;
                float b0 = sB1[c], b1 = sB1[c + 1];
                float f0 = sigmoidf_(acc[m][nf].x + b0);
                float f1 = sigmoidf_(acc[m][nf].y + b1);
                float f2 = sigmoidf_(acc[m][nf].z + b0);
                float f3 = sigmoidf_(acc[m][nf].w + b1);
                __nv_bfloat16 h0 = __float2bfloat16_rn(f0), h1 = __float2bfloat16_rn(f1);
                __nv_bfloat16 h2 = __float2bfloat16_rn(f2), h3 = __float2bfloat16_rn(f3);
                *(uint32_t*)(sHhi + r0 * LDH + c)       = pack_bf2(h0, h1);
                *(uint32_t*)(sHhi + (r0 + 8) * LDH + c) = pack_bf2(h2, h3);
                *(uint32_t*)(sHlo + r0 * LDH + c) =
                    pack_bf2(__float2bfloat16_rn(f0 - __bfloat162float(h0)),
                             __float2bfloat16_rn(f1 - __bfloat162float(h1)));
                *(uint32_t*)(sHlo + (r0 + 8) * LDH + c) =
                    pack_bf2(__float2bfloat16_rn(f2 - __bfloat162float(h2)),
                             __float2bfloat16_rn(f3 - __bfloat162float(h3)));
            }
        __syncthreads();   // all of sH visible to all warps

        // ---- GEMM2: [64,128] @ W2[128,128] ----
        float4 acc2[2][4];
        #pragma unroll
        for (int m = 0; m < 2; m++)
            #pragma unroll
            for (int nf = 0; nf < 4; nf++) acc2[m][nf] = make_float4(0.f, 0.f, 0.f, 0.f);

        #pragma unroll 1
        for (int ks = 0; ks < 8; ks++) {
            uint32_t ah[2][4], al[2][4];
            #pragma unroll
            for (int m = 0; m < 2; m++) {
                uint32_t ab = sb + SM_HHI +
                    (uint32_t)(((wm * 32 + m * 16 + arow) * LDH + ks * 16 + acolk) * 2);
                ldmx4(ah[m], ab);
                ldmx4(al[m], ab + (SM_HLO - SM_HHI));
            }
            #pragma unroll
            for (int nf = 0; nf < 4; nf++) {
                int fi = ks * 16 + wn * 4 + nf;
                uint2 bh = __ldg(&gW2hf[fi * 32 + lane]);
                uint2 bl = __ldg(&gW2lf[fi * 32 + lane]);
                #pragma unroll
                for (int m = 0; m < 2; m++) {
                    mma_bf16(acc2[m][nf], ah[m], bh);
                    mma_bf16(acc2[m][nf], ah[m], bl);
                    mma_bf16(acc2[m][nf], al[m], bh);
                }
            }
        }

        // ---- epilogue 2: softsign + red scatter into g_agg ----
        #pragma unroll
        for (int m = 0; m < 2; m++) {
            int r0 = wm * 32 + m * 16 + erow;
            int n0 = sRow[r0];
            int n1 = sRow[r0 + 8];
            #pragma unroll
            for (int nf = 0; nf < 4; nf++) {
                int c = wn * 32 + nf * 8 + ecol;
                float b0 = sB2[c], b1 = sB2[c + 1];
                red2(g_agg + (size_t)n0 * FDIM + c,
                     softsignf_(acc2[m][nf].x + b0), softsignf_(acc2[m][nf].y + b1));
                red2(g_agg + (size_t)n1 * FDIM + c,
                     softsignf_(acc2[m][nf].z + b0), softsignf_(acc2[m][nf].w + b1));
            }
        }
        __syncthreads();   // protect sA/sRow/sH before next tile overwrites
    }
}

// ===========================================================================
// Node kernel (R7 version, unchanged)
// ===========================================================================
#define TEN 64
#define NLDH 132
#define NLDN 388

__global__ void __launch_bounds__(256, 2)
node_kernel(const float* __restrict__ features,
            const float* __restrict__ time_emb,
            const float* __restrict__ Wf1,
            const float* __restrict__ bf1,
            const float* __restrict__ Wf2,
            const float* __restrict__ bf2,
            float* __restrict__ out)
{
    extern __shared__ float smemf[];
    float* sIn = smemf;

    const int tid = threadIdx.x;
    const int tx  = tid & 31;
    const int ty  = tid >> 5;
    const int n0  = blockIdx.x * TEN;

    for (int n = ty; n < TEN; n += 8) {
        int node = n0 + n;
        float4 a, g, t;
        if (node < N_NODES) {
            a = __ldg((const float4*)(features + (size_t)node * FDIM) + tx);
            g = *((const float4*)(g_agg + (size_t)node * FDIM) + tx);
            t = __ldg((const float4*)(time_emb + (size_t)node * FDIM) + tx);
        } else {
            a = g = t = make_float4(0.f, 0.f, 0.f, 0.f);
        }
        *(float4*)&sIn[n * NLDN + tx * 4] =
            make_float4(sigmoidf_(a.x), sigmoidf_(a.y), sigmoidf_(a.z), sigmoidf_(a.w));
        *(float4*)&sIn[n * NLDN + FDIM + tx * 4] =
            make_float4(sigmoidf_(g.x), sigmoidf_(g.y), sigmoidf_(g.z), sigmoidf_(g.w));
        *(float4*)&sIn[n * NLDN + 2 * FDIM + tx * 4] =
            make_float4(sigmoidf_(t.x), sigmoidf_(t.y), sigmoidf_(t.z), sigmoidf_(t.w));
    }
    __syncthreads();

    u64 acc[8][2];
    #pragma unroll
    for (int e = 0; e < 8; e++) { acc[e][0] = 0ull; acc[e][1] = 0ull; }

    const float* wBase = Wf1 + tx * 4;
    const float* aBase = sIn + (ty * 8) * NLDN;

    #pragma unroll 2
    for (int k = 0; k < 3 * FDIM; k += 4) {
        u64 w0a, w0b, w1a, w1b, w2a, w2b, w3a, w3b;
        ldg2x2(wBase + (k + 0) * FDIM, w0a, w0b);
        ldg2x2(wBase + (k + 1) * FDIM, w1a, w1b);
        ldg2x2(wBase + (k + 2) * FDIM, w2a, w2b);
        ldg2x2(wBase + (k + 3) * FDIM, w3a, w3b);
        #pragma unroll
        for (int e = 0; e < 8; e++) {
            float4 a = *(const float4*)(aBase + e * NLDN + k);
            u64 a0 = pack2(a.x), a1 = pack2(a.y), a2 = pack2(a.z), a3 = pack2(a.w);
            ffma2(acc[e][0], a0, w0a); ffma2(acc[e][1], a0, w0b);
            ffma2(acc[e][0], a1, w1a); ffma2(acc[e][1], a1, w1b);
            ffma2(acc[e][0], a2, w2a); ffma2(acc[e][1], a2, w2b);
            ffma2(acc[e][0], a3, w3a); ffma2(acc[e][1], a3, w3b);
        }
    }
    __syncthreads();

    float4 b1 = __ldg((const float4*)bf1 + tx);
    float* sH = smemf;
    #pragma unroll
    for (int e = 0; e < 8; e++) {
        float x0, x1, x2, x3;
        unpack2(acc[e][0], x0, x1);
        unpack2(acc[e][1], x2, x3);
        float4 h;
        h.x = sigmoidf_(x0 + b1.x);
        h.y = sigmoidf_(x1 + b1.y);
        h.z = sigmoidf_(x2 + b1.z);
        h.w = sigmoidf_(x3 + b1.w);
        *(float4*)&sH[(ty * 8 + e) * NLDH + tx * 4] = h;
    }
    __syncthreads();

    u64 acc2[8][2];
    #pragma unroll
    for (int e = 0; e < 8; e++) { acc2[e][0] = 0ull; acc2[e][1] = 0ull; }

    const float* w2Base = Wf2 + tx * 4;
    const float* hBase  = sH + (ty * 8) * NLDH;

    #pragma unroll 2
    for (int k = 0; k < FDIM; k += 4) {
        u64 w0a, w0b, w1a, w1b, w2a, w2b, w3a, w3b;
        ldg2x2(w2Base + (k + 0) * FDIM, w0a, w0b);
        ldg2x2(w2Base + (k + 1) * FDIM, w1a, w1b);
        ldg2x2(w2Base + (k + 2) * FDIM, w2a, w2b);
        ldg2x2(w2Base + (k + 3) * FDIM, w3a, w3b);
        #pragma unroll
        for (int e = 0; e < 8; e++) {
            float4 a = *(const float4*)(hBase + e * NLDH + k);
            u64 a0 = pack2(a.x), a1 = pack2(a.y), a2 = pack2(a.z), a3 = pack2(a.w);
            ffma2(acc2[e][0], a0, w0a); ffma2(acc2[e][1], a0, w0b);
            ffma2(acc2[e][0], a1, w1a); ffma2(acc2[e][1], a1, w1b);
            ffma2(acc2[e][0], a2, w2a); ffma2(acc2[e][1], a2, w2b);
            ffma2(acc2[e][0], a3, w3a); ffma2(acc2[e][1], a3, w3b);
        }
    }

    float4 b2 = __ldg((const float4*)bf2 + tx);
    #pragma unroll
    for (int e = 0; e < 8; e++) {
        int node = n0 + ty * 8 + e;
        if (node < N_NODES) {
            float x0, x1, x2, x3;
            unpack2(acc2[e][0], x0, x1);
            unpack2(acc2[e][1], x2, x3);
            float4 o;
            o.x = softsignf_(x0 + b2.x);
            o.y = softsignf_(x1 + b2.y);
            o.z = softsignf_(x2 + b2.z);
            o.w = softsignf_(x3 + b2.w);
            *(float4*)(out + (size_t)node * FDIM + tx * 4) = o;
        }
    }
}

// ===========================================================================
extern "C" void kernel_launch(void* const* d_in, const int* in_sizes, int n_in,
                              void* d_out, int out_size)
{
    const float* features = (const float*)d_in[0];
    const int*   rows     = (const int*)  d_in[1];
    const int*   cols     = (const int*)  d_in[2];
    const float* time_emb = (const float*)d_in[3];
    const float* Wm1      = (const float*)d_in[4];
    const float* bm1      = (const float*)d_in[5];
    const float* Wm2      = (const float*)d_in[6];
    const float* bm2      = (const float*)d_in[7];
    const float* Wf1      = (const float*)d_in[8];
    const float* bf1      = (const float*)d_in[9];
    const float* Wf2      = (const float*)d_in[10];
    const float* bf2      = (const float*)d_in[11];
    float* out = (float*)d_out;

    const int node_smem = TEN * NLDN * sizeof(float);
    cudaFuncSetAttribute(edge_mma_kernel, cudaFuncAttributeMaxDynamicSharedMemorySize, SM_TOTAL);
    cudaFuncSetAttribute(node_kernel,     cudaFuncAttributeMaxDynamicSharedMemorySize, node_smem);

    void* aggp = nullptr;
    cudaGetSymbolAddress(&aggp, g_agg);
    cudaMemsetAsync(aggp, 0, (size_t)N_NODES * FDIM * sizeof(float));

    uint2 *w1h, *w1l, *w2h, *w2l;
    cudaGetSymbolAddress((void**)&w1h, gW1hf);
    cudaGetSymbolAddress((void**)&w1l, gW1lf);
    cudaGetSymbolAddress((void**)&w2h, gW2hf);
    cudaGetSymbolAddress((void**)&w2l, gW2lf);

    prep_features<<<(N_NODES * FDIM + 255) / 256, 256>>>(features);
    prep_wfrag<<<32, 256>>>(Wm1, 16, w1h, w1l);
    prep_wfrag<<<16, 256>>>(Wm2,  8, w2h, w2l);

    edge_mma_kernel<<<296, 256, SM_TOTAL>>>(rows, cols, bm1, bm2);

    node_kernel<<<(N_NODES + TEN - 1) / TEN, 256, node_smem>>>(features, time_emb,
                                                               Wf1, bf1, Wf2, bf2, out);
}

// round 12
// speedup vs baseline: 1.2013x; 1.1199x over previous
#include <cuda_runtime.h>
#include <cuda_bf16.h>
#include <math.h>
#include <stdint.h>

#define N_NODES 10000
#define N_EDGES 640000
#define FDIM    128
#define TILE_E  64
#define N_TILES (N_EDGES / TILE_E)   // 10000

#define LDA 264   // smem stride (bf16) for A tile: 256 + 8
#define LDH 136   // smem stride (bf16) for h tile: 128 + 8

// ---- smem map (bytes), per CTA ~104KB -> 2 CTAs/SM ----
#define SM_ROW   0
#define SM_B1    256
#define SM_B2    768
#define SM_A     1280
#define SM_ALO   (SM_A   + TILE_E * LDA * 2)
#define SM_HHI   (SM_ALO + TILE_E * LDA * 2)
#define SM_HLO   (SM_HHI + TILE_E * LDH * 2)
#define SM_TOTAL (SM_HLO + TILE_E * LDH * 2)          // 103680

// ===========================================================================
__device__ float g_agg[N_NODES * FDIM];
__device__ __nv_bfloat16 gFhi[N_NODES * FDIM];
__device__ __nv_bfloat16 gFlo[N_NODES * FDIM];
__device__ uint2 gW1hf[256 * 32];
__device__ uint2 gW1lf[256 * 32];
__device__ uint2 gW2hf[128 * 32];
__device__ uint2 gW2lf[128 * 32];

typedef unsigned long long u64;

__device__ __forceinline__ float sigmoidf_(float x) { return 1.0f / (1.0f + __expf(-x)); }
__device__ __forceinline__ float softsignf_(float x) { return x / (1.0f + fabsf(x)); }

__device__ __forceinline__ uint32_t smem_u32(const void* p) {
    uint32_t a;
    asm("{ .reg .u64 t; cvta.to.shared.u64 t, %1; cvt.u32.u64 %0, t; }" : "=r"(a) : "l"(p));
    return a;
}
__device__ __forceinline__ uint32_t pack_bf2(__nv_bfloat16 lo, __nv_bfloat16 hi) {
    __nv_bfloat162 v; v.x = lo; v.y = hi;
    return *(uint32_t*)&v;
}
__device__ __forceinline__ void mma_bf16(float4& d, const uint32_t a[4], uint2 b) {
    asm volatile(
        "mma.sync.aligned.m16n8k16.row.col.f32.bf16.bf16.f32 "
        "{%0,%1,%2,%3}, {%4,%5,%6,%7}, {%8,%9}, {%0,%1,%2,%3};"
        : "+f"(d.x), "+f"(d.y), "+f"(d.z), "+f"(d.w)
        : "r"(a[0]), "r"(a[1]), "r"(a[2]), "r"(a[3]), "r"(b.x), "r"(b.y));
}
__device__ __forceinline__ void ldmx4(uint32_t r[4], uint32_t addr) {
    asm volatile("ldmatrix.sync.aligned.m8n8.x4.shared.b16 {%0,%1,%2,%3}, [%4];"
                 : "=r"(r[0]), "=r"(r[1]), "=r"(r[2]), "=r"(r[3]) : "r"(addr));
}
__device__ __forceinline__ void red2(float* p, float v0, float v1) {
    asm volatile("red.global.add.v2.f32 [%0], {%1, %2};" :: "l"(p), "f"(v0), "f"(v1) : "memory");
}
__device__ __forceinline__ void ffma2(u64& d, u64 a, u64 b) {
    asm("fma.rn.f32x2 %0, %1, %2, %0;" : "+l"(d) : "l"(a), "l"(b));
}
__device__ __forceinline__ u64 pack2(float s) {
    u64 r; asm("mov.b64 %0, {%1, %1};" : "=l"(r) : "f"(s)); return r;
}
__device__ __forceinline__ void unpack2(u64 v, float& lo, float& hi) {
    asm("mov.b64 {%0, %1}, %2;" : "=f"(lo), "=f"(hi) : "l"(v));
}
__device__ __forceinline__ void ldg2x2(const float* p, u64& d0, u64& d1) {
    asm("ld.global.nc.v2.b64 {%0, %1}, [%2];" : "=l"(d0), "=l"(d1) : "l"(p));
}

// ===========================================================================
// Prep kernels
// ===========================================================================
__global__ void prep_features(const float* __restrict__ f) {
    int i = blockIdx.x * 256 + threadIdx.x;
    if (i < N_NODES * FDIM) {
        float x = f[i];
        __nv_bfloat16 h = __float2bfloat16_rn(x);
        gFhi[i] = h;
        gFlo[i] = __float2bfloat16_rn(x - __bfloat162float(h));
    }
}
__global__ void prep_wfrag(const float* __restrict__ W, int ksteps,
                           uint2* __restrict__ outH, uint2* __restrict__ outL) {
    int i = blockIdx.x * 256 + threadIdx.x;
    if (i >= ksteps * 16 * 32) return;
    int lane = i & 31, fi = i >> 5;
    int kstep = fi >> 4, nfg = fi & 15;
    int n = nfg * 8 + (lane >> 2);
    __nv_bfloat16 hi[2][2], lo[2][2];
    #pragma unroll
    for (int j = 0; j < 2; j++)
        #pragma unroll
        for (int h = 0; h < 2; h++) {
            int k = kstep * 16 + j * 8 + (lane & 3) * 2 + h;
            float x = W[k * 128 + n];
            __nv_bfloat16 xh = __float2bfloat16_rn(x);
            hi[j][h] = xh;
            lo[j][h] = __float2bfloat16_rn(x - __bfloat162float(xh));
        }
    outH[i] = make_uint2(pack_bf2(hi[0][0], hi[0][1]), pack_bf2(hi[1][0], hi[1][1]));
    outL[i] = make_uint2(pack_bf2(lo[0][0], lo[0][1]), pack_bf2(lo[1][0], lo[1][1]));
}

// ===========================================================================
// Edge kernel: persistent, 296 CTAs x 256 threads, 2 CTAs/SM.
// Tile = 64 edges x 128 outputs, 8 warps = 2M x 4N. Split-bf16 mma.sync,
// software-pipelined: B fragments double-buffered one k-step ahead.
// ===========================================================================
__global__ void __launch_bounds__(256, 2)
edge_mma_kernel(const int* __restrict__ rows,
                const int* __restrict__ cols,
                const float* __restrict__ bm1,
                const float* __restrict__ bm2)
{
    extern __shared__ char smem[];
    int*   sRow = (int*)(smem + SM_ROW);
    float* sB1  = (float*)(smem + SM_B1);
    float* sB2  = (float*)(smem + SM_B2);
    __nv_bfloat16* sAhi = (__nv_bfloat16*)(smem + SM_A);
    __nv_bfloat16* sAlo = (__nv_bfloat16*)(smem + SM_ALO);
    __nv_bfloat16* sHhi = (__nv_bfloat16*)(smem + SM_HHI);
    __nv_bfloat16* sHlo = (__nv_bfloat16*)(smem + SM_HLO);

    const int tid  = threadIdx.x;
    const int lane = tid & 31;
    const int wid  = tid >> 5;
    const int wm   = wid & 1;   // M half
    const int wn   = wid >> 1;  // N quadrant
    const uint32_t sb = smem_u32(smem);

    if (tid < 128) { sB1[tid] = __ldg(bm1 + tid); sB2[tid] = __ldg(bm2 + tid); }

    const int arow  = lane & 15;
    const int acolk = (lane >> 4) * 8;
    const int erow  = lane >> 2;
    const int ecol  = (lane & 3) * 2;

    // per-warp base pointers into the weight-fragment tables
    const uint2* w1h = gW1hf + wn * 4 * 32 + lane;
    const uint2* w1l = gW1lf + wn * 4 * 32 + lane;
    const uint2* w2h = gW2hf + wn * 4 * 32 + lane;
    const uint2* w2l = gW2lf + wn * 4 * 32 + lane;

    for (int t = blockIdx.x; t < N_TILES; t += gridDim.x) {
        const int e0 = t * TILE_E;

        // ---- gather split features (64 edges x 4 parts = 256 threads) ----
        if (tid < TILE_E) sRow[tid] = __ldg(rows + e0 + tid);
        {
            int e = tid >> 2, part = tid & 3;
            int node = (part & 1) ? __ldg(cols + e0 + e) : __ldg(rows + e0 + e);
            const uint4* src = (const uint4*)(((part & 2) ? gFlo : gFhi) + (size_t)node * FDIM);
            uint4* dst = (uint4*)(((part & 2) ? sAlo : sAhi) + e * LDA + (part & 1) * FDIM);
            #pragma unroll
            for (int i = 0; i < 16; i++) dst[i] = __ldg(src + i);
        }
        __syncthreads();

        // ---- GEMM1: [64,256] @ W1[256,128], pipelined split-bf16 ----
        float4 acc[2][4];
        #pragma unroll
        for (int m = 0; m < 2; m++)
            #pragma unroll
            for (int nf = 0; nf < 4; nf++) acc[m][nf] = make_float4(0.f, 0.f, 0.f, 0.f);

        uint2 bh[2][4], bl[2][4];
        #pragma unroll
        for (int nf = 0; nf < 4; nf++) {        // prologue: B frags for ks=0
            bh[0][nf] = __ldg(w1h + nf * 32);
            bl[0][nf] = __ldg(w1l + nf * 32);
        }

        #pragma unroll 2
        for (int ks = 0; ks < 16; ks++) {
            const int cur = ks & 1, nxt = cur ^ 1;
            // A fragments for this ks (LDSM latency covered by B prefetch below)
            uint32_t ah[2][4], al[2][4];
            #pragma unroll
            for (int m = 0; m < 2; m++) {
                uint32_t ab = sb + SM_A +
                    (uint32_t)(((wm * 32 + m * 16 + arow) * LDA + ks * 16 + acolk) * 2);
                ldmx4(ah[m], ab);
                ldmx4(al[m], ab + (SM_ALO - SM_A));
            }
            // prefetch B fragments for ks+1
            if (ks < 15) {
                #pragma unroll
                for (int nf = 0; nf < 4; nf++) {
                    bh[nxt][nf] = __ldg(w1h + ((ks + 1) * 16 + nf) * 32);
                    bl[nxt][nf] = __ldg(w1l + ((ks + 1) * 16 + nf) * 32);
                }
            }
            #pragma unroll
            for (int nf = 0; nf < 4; nf++) {
                #pragma unroll
                for (int m = 0; m < 2; m++) {
                    mma_bf16(acc[m][nf], ah[m], bh[cur][nf]);
                    mma_bf16(acc[m][nf], ah[m], bl[cur][nf]);
                    mma_bf16(acc[m][nf], al[m], bh[cur][nf]);
                }
            }
        }

        // ---- epilogue 1: h = sigmoid(D1 + bm1) -> split bf16 -> sH ----
        #pragma unroll
        for (int m = 0; m < 2; m++)
            #pragma unroll
            for (int nf = 0; nf < 4; nf++) {
                int r0 = wm * 32 + m * 16 + erow;
                int c  = wn * 32 + nf * 8 + ecol;
                float b0 = sB1[c], b1 = sB1[c + 1];
                float f0 = sigmoidf_(acc[m][nf].x + b0);
                float f1 = sigmoidf_(acc[m][nf].y + b1);
                float f2 = sigmoidf_(acc[m][nf].z + b0);
                float f3 = sigmoidf_(acc[m][nf].w + b1);
                __nv_bfloat16 h0 = __float2bfloat16_rn(f0), h1 = __float2bfloat16_rn(f1);
                __nv_bfloat16 h2 = __float2bfloat16_rn(f2), h3 = __float2bfloat16_rn(f3);
                *(uint32_t*)(sHhi + r0 * LDH + c)       = pack_bf2(h0, h1);
                *(uint32_t*)(sHhi + (r0 + 8) * LDH + c) = pack_bf2(h2, h3);
                *(uint32_t*)(sHlo + r0 * LDH + c) =
                    pack_bf2(__float2bfloat16_rn(f0 - __bfloat162float(h0)),
                             __float2bfloat16_rn(f1 - __bfloat162float(h1)));
                *(uint32_t*)(sHlo + (r0 + 8) * LDH + c) =
                    pack_bf2(__float2bfloat16_rn(f2 - __bfloat162float(h2)),
                             __float2bfloat16_rn(f3 - __bfloat162float(h3)));
            }
        __syncthreads();

        // ---- GEMM2: [64,128] @ W2[128,128], pipelined ----
        float4 acc2[2][4];
        #pragma unroll
        for (int m = 0; m < 2; m++)
            #pragma unroll
            for (int nf = 0; nf < 4; nf++) acc2[m][nf] = make_float4(0.f, 0.f, 0.f, 0.f);

        #pragma unroll
        for (int nf = 0; nf < 4; nf++) {        // prologue: B frags for ks=0
            bh[0][nf] = __ldg(w2h + nf * 32);
            bl[0][nf] = __ldg(w2l + nf * 32);
        }

        #pragma unroll 2
        for (int ks = 0; ks < 8; ks++) {
            const int cur = ks & 1, nxt = cur ^ 1;
            uint32_t ah[2][4], al[2][4];
            #pragma unroll
            for (int m = 0; m < 2; m++) {
                uint32_t ab = sb + SM_HHI +
                    (uint32_t)(((wm * 32 + m * 16 + arow) * LDH + ks * 16 + acolk) * 2);
                ldmx4(ah[m], ab);
                ldmx4(al[m], ab + (SM_HLO - SM_HHI));
            }
            if (ks < 7) {
                #pragma unroll
                for (int nf = 0; nf < 4; nf++) {
                    bh[nxt][nf] = __ldg(w2h + ((ks + 1) * 16 + nf) * 32);
                    bl[nxt][nf] = __ldg(w2l + ((ks + 1) * 16 + nf) * 32);
                }
            }
            #pragma unroll
            for (int nf = 0; nf < 4; nf++) {
                #pragma unroll
                for (int m = 0; m < 2; m++) {
                    mma_bf16(acc2[m][nf], ah[m], bh[cur][nf]);
                    mma_bf16(acc2[m][nf], ah[m], bl[cur][nf]);
                    mma_bf16(acc2[m][nf], al[m], bh[cur][nf]);
                }
            }
        }

        // ---- epilogue 2: softsign + red scatter into g_agg ----
        #pragma unroll
        for (int m = 0; m < 2; m++) {
            int r0 = wm * 32 + m * 16 + erow;
            int n0 = sRow[r0];
            int n1 = sRow[r0 + 8];
            #pragma unroll
            for (int nf = 0; nf < 4; nf++) {
                int c = wn * 32 + nf * 8 + ecol;
                float b0 = sB2[c], b1 = sB2[c + 1];
                red2(g_agg + (size_t)n0 * FDIM + c,
                     softsignf_(acc2[m][nf].x + b0), softsignf_(acc2[m][nf].y + b1));
                red2(g_agg + (size_t)n1 * FDIM + c,
                     softsignf_(acc2[m][nf].z + b0), softsignf_(acc2[m][nf].w + b1));
            }
        }
        __syncthreads();
    }
}

// ===========================================================================
// Node kernel (R7 version, unchanged)
// ===========================================================================
#define TEN 64
#define NLDH 132
#define NLDN 388

__global__ void __launch_bounds__(256, 2)
node_kernel(const float* __restrict__ features,
            const float* __restrict__ time_emb,
            const float* __restrict__ Wf1,
            const float* __restrict__ bf1,
            const float* __restrict__ Wf2,
            const float* __restrict__ bf2,
            float* __restrict__ out)
{
    extern __shared__ float smemf[];
    float* sIn = smemf;

    const int tid = threadIdx.x;
    const int tx  = tid & 31;
    const int ty  = tid >> 5;
    const int n0  = blockIdx.x * TEN;

    for (int n = ty; n < TEN; n += 8) {
        int node = n0 + n;
        float4 a, g, t;
        if (node < N_NODES) {
            a = __ldg((const float4*)(features + (size_t)node * FDIM) + tx);
            g = *((const float4*)(g_agg + (size_t)node * FDIM) + tx);
            t = __ldg((const float4*)(time_emb + (size_t)node * FDIM) + tx);
        } else {
            a = g = t = make_float4(0.f, 0.f, 0.f, 0.f);
        }
        *(float4*)&sIn[n * NLDN + tx * 4] =
            make_float4(sigmoidf_(a.x), sigmoidf_(a.y), sigmoidf_(a.z), sigmoidf_(a.w));
        *(float4*)&sIn[n * NLDN + FDIM + tx * 4] =
            make_float4(sigmoidf_(g.x), sigmoidf_(g.y), sigmoidf_(g.z), sigmoidf_(g.w));
        *(float4*)&sIn[n * NLDN + 2 * FDIM + tx * 4] =
            make_float4(sigmoidf_(t.x), sigmoidf_(t.y), sigmoidf_(t.z), sigmoidf_(t.w));
    }
    __syncthreads();

    u64 acc[8][2];
    #pragma unroll
    for (int e = 0; e < 8; e++) { acc[e][0] = 0ull; acc[e][1] = 0ull; }

    const float* wBase = Wf1 + tx * 4;
    const float* aBase = sIn + (ty * 8) * NLDN;

    #pragma unroll 2
    for (int k = 0; k < 3 * FDIM; k += 4) {
        u64 w0a, w0b, w1a, w1b, w2a, w2b, w3a, w3b;
        ldg2x2(wBase + (k + 0) * FDIM, w0a, w0b);
        ldg2x2(wBase + (k + 1) * FDIM, w1a, w1b);
        ldg2x2(wBase + (k + 2) * FDIM, w2a, w2b);
        ldg2x2(wBase + (k + 3) * FDIM, w3a, w3b);
        #pragma unroll
        for (int e = 0; e < 8; e++) {
            float4 a = *(const float4*)(aBase + e * NLDN + k);
            u64 a0 = pack2(a.x), a1 = pack2(a.y), a2 = pack2(a.z), a3 = pack2(a.w);
            ffma2(acc[e][0], a0, w0a); ffma2(acc[e][1], a0, w0b);
            ffma2(acc[e][0], a1, w1a); ffma2(acc[e][1], a1, w1b);
            ffma2(acc[e][0], a2, w2a); ffma2(acc[e][1], a2, w2b);
            ffma2(acc[e][0], a3, w3a); ffma2(acc[e][1], a3, w3b);
        }
    }
    __syncthreads();

    float4 b1 = __ldg((const float4*)bf1 + tx);
    float* sH = smemf;
    #pragma unroll
    for (int e = 0; e < 8; e++) {
        float x0, x1, x2, x3;
        unpack2(acc[e][0], x0, x1);
        unpack2(acc[e][1], x2, x3);
        float4 h;
        h.x = sigmoidf_(x0 + b1.x);
        h.y = sigmoidf_(x1 + b1.y);
        h.z = sigmoidf_(x2 + b1.z);
        h.w = sigmoidf_(x3 + b1.w);
        *(float4*)&sH[(ty * 8 + e) * NLDH + tx * 4] = h;
    }
    __syncthreads();

    u64 acc2[8][2];
    #pragma unroll
    for (int e = 0; e < 8; e++) { acc2[e][0] = 0ull; acc2[e][1] = 0ull; }

    const float* w2Base = Wf2 + tx * 4;
    const float* hBase  = sH + (ty * 8) * NLDH;

    #pragma unroll 2
    for (int k = 0; k < FDIM; k += 4) {
        u64 w0a, w0b, w1a, w1b, w2a, w2b, w3a, w3b;
        ldg2x2(w2Base + (k + 0) * FDIM, w0a, w0b);
        ldg2x2(w2Base + (k + 1) * FDIM, w1a, w1b);
        ldg2x2(w2Base + (k + 2) * FDIM, w2a, w2b);
        ldg2x2(w2Base + (k + 3) * FDIM, w3a, w3b);
        #pragma unroll
        for (int e = 0; e < 8; e++) {
            float4 a = *(const float4*)(hBase + e * NLDH + k);
            u64 a0 = pack2(a.x), a1 = pack2(a.y), a2 = pack2(a.z), a3 = pack2(a.w);
            ffma2(acc2[e][0], a0, w0a); ffma2(acc2[e][1], a0, w0b);
            ffma2(acc2[e][0], a1, w1a); ffma2(acc2[e][1], a1, w1b);
            ffma2(acc2[e][0], a2, w2a); ffma2(acc2[e][1], a2, w2b);
            ffma2(acc2[e][0], a3, w3a); ffma2(acc2[e][1], a3, w3b);
        }
    }

    float4 b2 = __ldg((const float4*)bf2 + tx);
    #pragma unroll
    for (int e = 0; e < 8; e++) {
        int node = n0 + ty * 8 + e;
        if (node < N_NODES) {
            float x0, x1, x2, x3;
            unpack2(acc2[e][0], x0, x1);
            unpack2(acc2[e][1], x2, x3);
            float4 o;
            o.x = softsignf_(x0 + b2.x);
            o.y = softsignf_(x1 + b2.y);
            o.z = softsignf_(x2 + b2.z);
            o.w = softsignf_(x3 + b2.w);
            *(float4*)(out + (size_t)node * FDIM + tx * 4) = o;
        }
    }
}

// ===========================================================================
extern "C" void kernel_launch(void* const* d_in, const int* in_sizes, int n_in,
                              void* d_out, int out_size)
{
    const float* features = (const float*)d_in[0];
    const int*   rows     = (const int*)  d_in[1];
    const int*   cols     = (const int*)  d_in[2];
    const float* time_emb = (const float*)d_in[3];
    const float* Wm1      = (const float*)d_in[4];
    const float* bm1      = (const float*)d_in[5];
    const float* Wm2      = (const float*)d_in[6];
    const float* bm2      = (const float*)d_in[7];
    const float* Wf1      = (const float*)d_in[8];
    const float* bf1      = (const float*)d_in[9];
    const float* Wf2      = (const float*)d_in[10];
    const float* bf2      = (const float*)d_in[11];
    float* out = (float*)d_out;

    const int node_smem = TEN * NLDN * sizeof(float);
    cudaFuncSetAttribute(edge_mma_kernel, cudaFuncAttributeMaxDynamicSharedMemorySize, SM_TOTAL);
    cudaFuncSetAttribute(node_kernel,     cudaFuncAttributeMaxDynamicSharedMemorySize, node_smem);

    void* aggp = nullptr;
    cudaGetSymbolAddress(&aggp, g_agg);
    cudaMemsetAsync(aggp, 0, (size_t)N_NODES * FDIM * sizeof(float));

    uint2 *w1h, *w1l, *w2h, *w2l;
    cudaGetSymbolAddress((void**)&w1h, gW1hf);
    cudaGetSymbolAddress((void**)&w1l, gW1lf);
    cudaGetSymbolAddress((void**)&w2h, gW2hf);
    cudaGetSymbolAddress((void**)&w2l, gW2lf);

    prep_features<<<(N_NODES * FDIM + 255) / 256, 256>>>(features);
    prep_wfrag<<<32, 256>>>(Wm1, 16, w1h, w1l);
    prep_wfrag<<<16, 256>>>(Wm2,  8, w2h, w2l);

    edge_mma_kernel<<<296, 256, SM_TOTAL>>>(rows, cols, bm1, bm2);

    node_kernel<<<(N_NODES + TEN - 1) / TEN, 256, node_smem>>>(features, time_emb,
                                                               Wf1, bf1, Wf2, bf2, out);
}

// round 13
// speedup vs baseline: 2.1842x; 1.8182x over previous
#include <cuda_runtime.h>
#include <cuda_fp16.h>
#include <math.h>
#include <stdint.h>

#define N_NODES 10000
#define N_EDGES 640000
#define FDIM    128
#define TILE_E  64
#define N_TILES (N_EDGES / TILE_E)   // 10000

#define LDA 264   // smem stride (fp16) for A tile: 256 + 8
#define LDH 136   // smem stride (fp16) for h tile: 128 + 8

// ---- smem map (bytes), per CTA ~52KB -> 2 CTAs/SM ----
#define SM_ROW   0
#define SM_B1    256
#define SM_B2    768
#define SM_A     1280
#define SM_H     (SM_A + TILE_E * LDA * 2)            // 35072
#define SM_TOTAL (SM_H + TILE_E * LDH * 2)            // 52480

// ===========================================================================
__device__ float  g_agg[N_NODES * FDIM];
__device__ __half gF[N_NODES * FDIM];                 // fp16 features
// weight fragments (fp16): index [frag_id][lane], frag_id = kstep*16 + nfrag
__device__ uint2 gW1f[256 * 32];
__device__ uint2 gW2f[128 * 32];

typedef unsigned long long u64;

__device__ __forceinline__ float sigmoidf_(float x) { return 1.0f / (1.0f + __expf(-x)); }
__device__ __forceinline__ float softsignf_(float x) { return x / (1.0f + fabsf(x)); }

__device__ __forceinline__ uint32_t smem_u32(const void* p) {
    uint32_t a;
    asm("{ .reg .u64 t; cvta.to.shared.u64 t, %1; cvt.u32.u64 %0, t; }" : "=r"(a) : "l"(p));
    return a;
}
__device__ __forceinline__ uint32_t pack_h2(__half lo, __half hi) {
    __half2 v; v.x = lo; v.y = hi;
    return *(uint32_t*)&v;
}
// d += A(16x16) @ B(16x8), fp16 in, f32 accum
__device__ __forceinline__ void mma_f16(float4& d, const uint32_t a[4], uint2 b) {
    asm volatile(
        "mma.sync.aligned.m16n8k16.row.col.f32.f16.f16.f32 "
        "{%0,%1,%2,%3}, {%4,%5,%6,%7}, {%8,%9}, {%0,%1,%2,%3};"
        : "+f"(d.x), "+f"(d.y), "+f"(d.z), "+f"(d.w)
        : "r"(a[0]), "r"(a[1]), "r"(a[2]), "r"(a[3]), "r"(b.x), "r"(b.y));
}
__device__ __forceinline__ void ldmx4(uint32_t r[4], uint32_t addr) {
    asm volatile("ldmatrix.sync.aligned.m8n8.x4.shared.b16 {%0,%1,%2,%3}, [%4];"
                 : "=r"(r[0]), "=r"(r[1]), "=r"(r[2]), "=r"(r[3]) : "r"(addr));
}
__device__ __forceinline__ void red2(float* p, float v0, float v1) {
    asm volatile("red.global.add.v2.f32 [%0], {%1, %2};" :: "l"(p), "f"(v0), "f"(v1) : "memory");
}
// f32x2 helpers (node kernel, validated R7)
__device__ __forceinline__ void ffma2(u64& d, u64 a, u64 b) {
    asm("fma.rn.f32x2 %0, %1, %2, %0;" : "+l"(d) : "l"(a), "l"(b));
}
__device__ __forceinline__ u64 pack2(float s) {
    u64 r; asm("mov.b64 %0, {%1, %1};" : "=l"(r) : "f"(s)); return r;
}
__device__ __forceinline__ void unpack2(u64 v, float& lo, float& hi) {
    asm("mov.b64 {%0, %1}, %2;" : "=f"(lo), "=f"(hi) : "l"(v));
}
__device__ __forceinline__ void ldg2x2(const float* p, u64& d0, u64& d1) {
    asm("ld.global.nc.v2.b64 {%0, %1}, [%2];" : "=l"(d0), "=l"(d1) : "l"(p));
}

// ===========================================================================
// Prep kernels
// ===========================================================================
__global__ void prep_features(const float* __restrict__ f) {
    int i = blockIdx.x * 256 + threadIdx.x;
    if (i < N_NODES * FDIM) gF[i] = __float2half_rn(f[i]);
}
__global__ void prep_wfrag(const float* __restrict__ W, int ksteps,
                           uint2* __restrict__ outF) {
    int i = blockIdx.x * 256 + threadIdx.x;
    if (i >= ksteps * 16 * 32) return;
    int lane = i & 31, fi = i >> 5;
    int kstep = fi >> 4, nfg = fi & 15;
    int n = nfg * 8 + (lane >> 2);
    __half v[2][2];
    #pragma unroll
    for (int j = 0; j < 2; j++)
        #pragma unroll
        for (int h = 0; h < 2; h++) {
            int k = kstep * 16 + j * 8 + (lane & 3) * 2 + h;
            v[j][h] = __float2half_rn(W[k * 128 + n]);
        }
    outF[i] = make_uint2(pack_h2(v[0][0], v[0][1]), pack_h2(v[1][0], v[1][1]));
}

// ===========================================================================
// Edge kernel: persistent, 296 CTAs x 256 threads, 2 CTAs/SM.
// Tile = 64 edges x 128 outputs, 8 warps = 2M x 4N. Single-pass fp16 mma,
// B fragments double-buffered one k-step ahead.
// ===========================================================================
__global__ void __launch_bounds__(256, 2)
edge_mma_kernel(const int* __restrict__ rows,
                const int* __restrict__ cols,
                const float* __restrict__ bm1,
                const float* __restrict__ bm2)
{
    extern __shared__ char smem[];
    int*    sRow = (int*)(smem + SM_ROW);
    float*  sB1  = (float*)(smem + SM_B1);
    float*  sB2  = (float*)(smem + SM_B2);
    __half* sA   = (__half*)(smem + SM_A);
    __half* sH   = (__half*)(smem + SM_H);

    const int tid  = threadIdx.x;
    const int lane = tid & 31;
    const int wid  = tid >> 5;
    const int wm   = wid & 1;   // M half
    const int wn   = wid >> 1;  // N quadrant
    const uint32_t sb = smem_u32(smem);

    if (tid < 128) { sB1[tid] = __ldg(bm1 + tid); sB2[tid] = __ldg(bm2 + tid); }

    const int arow  = lane & 15;
    const int acolk = (lane >> 4) * 8;
    const int erow  = lane >> 2;
    const int ecol  = (lane & 3) * 2;

    const uint2* w1f = gW1f + wn * 4 * 32 + lane;
    const uint2* w2f = gW2f + wn * 4 * 32 + lane;

    for (int t = blockIdx.x; t < N_TILES; t += gridDim.x) {
        const int e0 = t * TILE_E;

        // ---- gather fp16 features: 64 edges x 2 halves x 16 uint4 ----
        if (tid < TILE_E) sRow[tid] = __ldg(rows + e0 + tid);
        {
            int e = tid >> 2, q = tid & 3;          // q: bit0 = src/dst, bit1 = row segment
            int half = q & 1, seg = q >> 1;
            int node = half ? __ldg(cols + e0 + e) : __ldg(rows + e0 + e);
            const uint4* src = (const uint4*)(gF + (size_t)node * FDIM) + seg * 8;
            uint4* dst = (uint4*)(sA + e * LDA + half * FDIM) + seg * 8;
            #pragma unroll
            for (int i = 0; i < 8; i++) dst[i] = __ldg(src + i);
        }
        __syncthreads();

        // ---- GEMM1: [64,256] @ W1[256,128], fp16, pipelined ----
        float4 acc[2][4];
        #pragma unroll
        for (int m = 0; m < 2; m++)
            #pragma unroll
            for (int nf = 0; nf < 4; nf++) acc[m][nf] = make_float4(0.f, 0.f, 0.f, 0.f);

        uint2 bf[2][4];
        #pragma unroll
        for (int nf = 0; nf < 4; nf++) bf[0][nf] = __ldg(w1f + nf * 32);

        #pragma unroll 2
        for (int ks = 0; ks < 16; ks++) {
            const int cur = ks & 1, nxt = cur ^ 1;
            uint32_t ah[2][4];
            #pragma unroll
            for (int m = 0; m < 2; m++) {
                uint32_t ab = sb + SM_A +
                    (uint32_t)(((wm * 32 + m * 16 + arow) * LDA + ks * 16 + acolk) * 2);
                ldmx4(ah[m], ab);
            }
            if (ks < 15) {
                #pragma unroll
                for (int nf = 0; nf < 4; nf++)
                    bf[nxt][nf] = __ldg(w1f + ((ks + 1) * 16 + nf) * 32);
            }
            #pragma unroll
            for (int nf = 0; nf < 4; nf++)
                #pragma unroll
                for (int m = 0; m < 2; m++)
                    mma_f16(acc[m][nf], ah[m], bf[cur][nf]);
        }

        // ---- epilogue 1: h = sigmoid(D1 + bm1) -> fp16 -> sH ----
        #pragma unroll
        for (int m = 0; m < 2; m++)
            #pragma unroll
            for (int nf = 0; nf < 4; nf++) {
                int r0 = wm * 32 + m * 16 + erow;
                int c  = wn * 32 + nf * 8 + ecol;
                float b0 = sB1[c], b1 = sB1[c + 1];
                *(uint32_t*)(sH + r0 * LDH + c) =
                    pack_h2(__float2half_rn(sigmoidf_(acc[m][nf].x + b0)),
                            __float2half_rn(sigmoidf_(acc[m][nf].y + b1)));
                *(uint32_t*)(sH + (r0 + 8) * LDH + c) =
                    pack_h2(__float2half_rn(sigmoidf_(acc[m][nf].z + b0)),
                            __float2half_rn(sigmoidf_(acc[m][nf].w + b1)));
            }
        __syncthreads();

        // ---- GEMM2: [64,128] @ W2[128,128], fp16, pipelined ----
        float4 acc2[2][4];
        #pragma unroll
        for (int m = 0; m < 2; m++)
            #pragma unroll
            for (int nf = 0; nf < 4; nf++) acc2[m][nf] = make_float4(0.f, 0.f, 0.f, 0.f);

        #pragma unroll
        for (int nf = 0; nf < 4; nf++) bf[0][nf] = __ldg(w2f + nf * 32);

        #pragma unroll 2
        for (int ks = 0; ks < 8; ks++) {
            const int cur = ks & 1, nxt = cur ^ 1;
            uint32_t ah[2][4];
            #pragma unroll
            for (int m = 0; m < 2; m++) {
                uint32_t ab = sb + SM_H +
                    (uint32_t)(((wm * 32 + m * 16 + arow) * LDH + ks * 16 + acolk) * 2);
                ldmx4(ah[m], ab);
            }
            if (ks < 7) {
                #pragma unroll
                for (int nf = 0; nf < 4; nf++)
                    bf[nxt][nf] = __ldg(w2f + ((ks + 1) * 16 + nf) * 32);
            }
            #pragma unroll
            for (int nf = 0; nf < 4; nf++)
                #pragma unroll
                for (int m = 0; m < 2; m++)
                    mma_f16(acc2[m][nf], ah[m], bf[cur][nf]);
        }

        // ---- epilogue 2: softsign + red scatter into g_agg ----
        #pragma unroll
        for (int m = 0; m < 2; m++) {
            int r0 = wm * 32 + m * 16 + erow;
            int n0 = sRow[r0];
            int n1 = sRow[r0 + 8];
            #pragma unroll
            for (int nf = 0; nf < 4; nf++) {
                int c = wn * 32 + nf * 8 + ecol;
                float b0 = sB2[c], b1 = sB2[c + 1];
                red2(g_agg + (size_t)n0 * FDIM + c,
                     softsignf_(acc2[m][nf].x + b0), softsignf_(acc2[m][nf].y + b1));
                red2(g_agg + (size_t)n1 * FDIM + c,
                     softsignf_(acc2[m][nf].z + b0), softsignf_(acc2[m][nf].w + b1));
            }
        }
        __syncthreads();
    }
}

// ===========================================================================
// Node kernel (R7 version, unchanged; fp32 f32x2 — keeps output precision)
// ===========================================================================
#define TEN 64
#define NLDH 132
#define NLDN 388

__global__ void __launch_bounds__(256, 2)
node_kernel(const float* __restrict__ features,
            const float* __restrict__ time_emb,
            const float* __restrict__ Wf1,
            const float* __restrict__ bf1,
            const float* __restrict__ Wf2,
            const float* __restrict__ bf2,
            float* __restrict__ out)
{
    extern __shared__ float smemf[];
    float* sIn = smemf;

    const int tid = threadIdx.x;
    const int tx  = tid & 31;
    const int ty  = tid >> 5;
    const int n0  = blockIdx.x * TEN;

    for (int n = ty; n < TEN; n += 8) {
        int node = n0 + n;
        float4 a, g, t;
        if (node < N_NODES) {
            a = __ldg((const float4*)(features + (size_t)node * FDIM) + tx);
            g = *((const float4*)(g_agg + (size_t)node * FDIM) + tx);
            t = __ldg((const float4*)(time_emb + (size_t)node * FDIM) + tx);
        } else {
            a = g = t = make_float4(0.f, 0.f, 0.f, 0.f);
        }
        *(float4*)&sIn[n * NLDN + tx * 4] =
            make_float4(sigmoidf_(a.x), sigmoidf_(a.y), sigmoidf_(a.z), sigmoidf_(a.w));
        *(float4*)&sIn[n * NLDN + FDIM + tx * 4] =
            make_float4(sigmoidf_(g.x), sigmoidf_(g.y), sigmoidf_(g.z), sigmoidf_(g.w));
        *(float4*)&sIn[n * NLDN + 2 * FDIM + tx * 4] =
            make_float4(sigmoidf_(t.x), sigmoidf_(t.y), sigmoidf_(t.z), sigmoidf_(t.w));
    }
    __syncthreads();

    u64 acc[8][2];
    #pragma unroll
    for (int e = 0; e < 8; e++) { acc[e][0] = 0ull; acc[e][1] = 0ull; }

    const float* wBase = Wf1 + tx * 4;
    const float* aBase = sIn + (ty * 8) * NLDN;

    #pragma unroll 2
    for (int k = 0; k < 3 * FDIM; k += 4) {
        u64 w0a, w0b, w1a, w1b, w2a, w2b, w3a, w3b;
        ldg2x2(wBase + (k + 0) * FDIM, w0a, w0b);
        ldg2x2(wBase + (k + 1) * FDIM, w1a, w1b);
        ldg2x2(wBase + (k + 2) * FDIM, w2a, w2b);
        ldg2x2(wBase + (k + 3) * FDIM, w3a, w3b);
        #pragma unroll
        for (int e = 0; e < 8; e++) {
            float4 a = *(const float4*)(aBase + e * NLDN + k);
            u64 a0 = pack2(a.x), a1 = pack2(a.y), a2 = pack2(a.z), a3 = pack2(a.w);
            ffma2(acc[e][0], a0, w0a); ffma2(acc[e][1], a0, w0b);
            ffma2(acc[e][0], a1, w1a); ffma2(acc[e][1], a1, w1b);
            ffma2(acc[e][0], a2, w2a); ffma2(acc[e][1], a2, w2b);
            ffma2(acc[e][0], a3, w3a); ffma2(acc[e][1], a3, w3b);
        }
    }
    __syncthreads();

    float4 b1 = __ldg((const float4*)bf1 + tx);
    float* sHf = smemf;
    #pragma unroll
    for (int e = 0; e < 8; e++) {
        float x0, x1, x2, x3;
        unpack2(acc[e][0], x0, x1);
        unpack2(acc[e][1], x2, x3);
        float4 h;
        h.x = sigmoidf_(x0 + b1.x);
        h.y = sigmoidf_(x1 + b1.y);
        h.z = sigmoidf_(x2 + b1.z);
        h.w = sigmoidf_(x3 + b1.w);
        *(float4*)&sHf[(ty * 8 + e) * NLDH + tx * 4] = h;
    }
    __syncthreads();

    u64 acc2[8][2];
    #pragma unroll
    for (int e = 0; e < 8; e++) { acc2[e][0] = 0ull; acc2[e][1] = 0ull; }

    const float* w2Base = Wf2 + tx * 4;
    const float* hBase  = sHf + (ty * 8) * NLDH;

    #pragma unroll 2
    for (int k = 0; k < FDIM; k += 4) {
        u64 w0a, w0b, w1a, w1b, w2a, w2b, w3a, w3b;
        ldg2x2(w2Base + (k + 0) * FDIM, w0a, w0b);
        ldg2x2(w2Base + (k + 1) * FDIM, w1a, w1b);
        ldg2x2(w2Base + (k + 2) * FDIM, w2a, w2b);
        ldg2x2(w2Base + (k + 3) * FDIM, w3a, w3b);
        #pragma unroll
        for (int e = 0; e < 8; e++) {
            float4 a = *(const float4*)(hBase + e * NLDH + k);
            u64 a0 = pack2(a.x), a1 = pack2(a.y), a2 = pack2(a.z), a3 = pack2(a.w);
            ffma2(acc2[e][0], a0, w0a); ffma2(acc2[e][1], a0, w0b);
            ffma2(acc2[e][0], a1, w1a); ffma2(acc2[e][1], a1, w1b);
            ffma2(acc2[e][0], a2, w2a); ffma2(acc2[e][1], a2, w2b);
            ffma2(acc2[e][0], a3, w3a); ffma2(acc2[e][1], a3, w3b);
        }
    }

    float4 b2 = __ldg((const float4*)bf2 + tx);
    #pragma unroll
    for (int e = 0; e < 8; e++) {
        int node = n0 + ty * 8 + e;
        if (node < N_NODES) {
            float x0, x1, x2, x3;
            unpack2(acc2[e][0], x0, x1);
            unpack2(acc2[e][1], x2, x3);
            float4 o;
            o.x = softsignf_(x0 + b2.x);
            o.y = softsignf_(x1 + b2.y);
            o.z = softsignf_(x2 + b2.z);
            o.w = softsignf_(x3 + b2.w);
            *(float4*)(out + (size_t)node * FDIM + tx * 4) = o;
        }
    }
}

// ===========================================================================
extern "C" void kernel_launch(void* const* d_in, const int* in_sizes, int n_in,
                              void* d_out, int out_size)
{
    const float* features = (const float*)d_in[0];
    const int*   rows     = (const int*)  d_in[1];
    const int*   cols     = (const int*)  d_in[2];
    const float* time_emb = (const float*)d_in[3];
    const float* Wm1      = (const float*)d_in[4];
    const float* bm1      = (const float*)d_in[5];
    const float* Wm2      = (const float*)d_in[6];
    const float* bm2      = (const float*)d_in[7];
    const float* Wf1      = (const float*)d_in[8];
    const float* bf1      = (const float*)d_in[9];
    const float* Wf2      = (const float*)d_in[10];
    const float* bf2      = (const float*)d_in[11];
    float* out = (float*)d_out;

    const int node_smem = TEN * NLDN * sizeof(float);
    cudaFuncSetAttribute(edge_mma_kernel, cudaFuncAttributeMaxDynamicSharedMemorySize, SM_TOTAL);
    cudaFuncSetAttribute(node_kernel,     cudaFuncAttributeMaxDynamicSharedMemorySize, node_smem);

    void* aggp = nullptr;
    cudaGetSymbolAddress(&aggp, g_agg);
    cudaMemsetAsync(aggp, 0, (size_t)N_NODES * FDIM * sizeof(float));

    uint2 *w1f, *w2f;
    cudaGetSymbolAddress((void**)&w1f, gW1f);
    cudaGetSymbolAddress((void**)&w2f, gW2f);

    prep_features<<<(N_NODES * FDIM + 255) / 256, 256>>>(features);
    prep_wfrag<<<32, 256>>>(Wm1, 16, w1f);
    prep_wfrag<<<16, 256>>>(Wm2,  8, w2f);

    edge_mma_kernel<<<296, 256, SM_TOTAL>>>(rows, cols, bm1, bm2);

    node_kernel<<<(N_NODES + TEN - 1) / TEN, 256, node_smem>>>(features, time_emb,
                                                               Wf1, bf1, Wf2, bf2, out);
}

// round 14
// speedup vs baseline: 2.4922x; 1.1410x over previous
#include <cuda_runtime.h>
#include <cuda_fp16.h>
#include <math.h>
#include <stdint.h>

#define N_NODES 10000
#define N_EDGES 640000
#define FDIM    128
#define TILE_E  64
#define N_TILES (N_EDGES / TILE_E)   // 10000

#define LDA 264   // smem stride (fp16) for A tile: 256 + 8
#define LDH 136   // smem stride (fp16) for h tile: 128 + 8
#define ABUF (TILE_E * LDA * 2)      // 33792 bytes per A buffer

// ---- smem map (bytes), per CTA ~84.5KB -> 2 CTAs/SM ----
#define SM_ROW   0                    // 2 x 64 ints (ping-pong)
#define SM_B1    512
#define SM_B2    1024
#define SM_A     1536                 // 2 x ABUF
#define SM_H     (SM_A + 2 * ABUF)    // 69120
#define SM_TOTAL (SM_H + TILE_E * LDH * 2)   // 86528

// ===========================================================================
__device__ float  g_agg[N_NODES * FDIM];
__device__ __half gF[N_NODES * FDIM];
__device__ uint2 gW1f[256 * 32];
__device__ uint2 gW2f[128 * 32];

typedef unsigned long long u64;

__device__ __forceinline__ float sigmoidf_(float x) { return 1.0f / (1.0f + __expf(-x)); }
__device__ __forceinline__ float softsignf_(float x) { return x / (1.0f + fabsf(x)); }

__device__ __forceinline__ uint32_t smem_u32(const void* p) {
    uint32_t a;
    asm("{ .reg .u64 t; cvta.to.shared.u64 t, %1; cvt.u32.u64 %0, t; }" : "=r"(a) : "l"(p));
    return a;
}
__device__ __forceinline__ uint32_t pack_h2(__half lo, __half hi) {
    __half2 v; v.x = lo; v.y = hi;
    return *(uint32_t*)&v;
}
__device__ __forceinline__ void mma_f16(float4& d, const uint32_t a[4], uint2 b) {
    asm volatile(
        "mma.sync.aligned.m16n8k16.row.col.f32.f16.f16.f32 "
        "{%0,%1,%2,%3}, {%4,%5,%6,%7}, {%8,%9}, {%0,%1,%2,%3};"
        : "+f"(d.x), "+f"(d.y), "+f"(d.z), "+f"(d.w)
        : "r"(a[0]), "r"(a[1]), "r"(a[2]), "r"(a[3]), "r"(b.x), "r"(b.y));
}
__device__ __forceinline__ void ldmx4(uint32_t r[4], uint32_t addr) {
    asm volatile("ldmatrix.sync.aligned.m8n8.x4.shared.b16 {%0,%1,%2,%3}, [%4];"
                 : "=r"(r[0]), "=r"(r[1]), "=r"(r[2]), "=r"(r[3]) : "r"(addr));
}
__device__ __forceinline__ void red2(float* p, float v0, float v1) {
    asm volatile("red.global.add.v2.f32 [%0], {%1, %2};" :: "l"(p), "f"(v0), "f"(v1) : "memory");
}
// cp.async 16B, L1-bypassing (.cg): keeps weight fragments resident in L1
__device__ __forceinline__ void cpa16(uint32_t saddr, const void* gaddr) {
    asm volatile("cp.async.cg.shared.global [%0], [%1], 16;" :: "r"(saddr), "l"(gaddr));
}
#define CP_COMMIT() asm volatile("cp.async.commit_group;" ::: "memory")
#define CP_WAIT0()  asm volatile("cp.async.wait_group 0;" ::: "memory")
// f32x2 helpers (node kernel, validated R7)
__device__ __forceinline__ void ffma2(u64& d, u64 a, u64 b) {
    asm("fma.rn.f32x2 %0, %1, %2, %0;" : "+l"(d) : "l"(a), "l"(b));
}
__device__ __forceinline__ u64 pack2(float s) {
    u64 r; asm("mov.b64 %0, {%1, %1};" : "=l"(r) : "f"(s)); return r;
}
__device__ __forceinline__ void unpack2(u64 v, float& lo, float& hi) {
    asm("mov.b64 {%0, %1}, %2;" : "=f"(lo), "=f"(hi) : "l"(v));
}
__device__ __forceinline__ void ldg2x2(const float* p, u64& d0, u64& d1) {
    asm("ld.global.nc.v2.b64 {%0, %1}, [%2];" : "=l"(d0), "=l"(d1) : "l"(p));
}

// ===========================================================================
// Prep kernels
// ===========================================================================
__global__ void prep_features(const float* __restrict__ f) {
    int i = blockIdx.x * 256 + threadIdx.x;
    if (i < N_NODES * FDIM) gF[i] = __float2half_rn(f[i]);
}
__global__ void prep_wfrag(const float* __restrict__ W, int ksteps,
                           uint2* __restrict__ outF) {
    int i = blockIdx.x * 256 + threadIdx.x;
    if (i >= ksteps * 16 * 32) return;
    int lane = i & 31, fi = i >> 5;
    int kstep = fi >> 4, nfg = fi & 15;
    int n = nfg * 8 + (lane >> 2);
    __half v[2][2];
    #pragma unroll
    for (int j = 0; j < 2; j++)
        #pragma unroll
        for (int h = 0; h < 2; h++) {
            int k = kstep * 16 + j * 8 + (lane & 3) * 2 + h;
            v[j][h] = __float2half_rn(W[k * 128 + n]);
        }
    outF[i] = make_uint2(pack_h2(v[0][0], v[0][1]), pack_h2(v[1][0], v[1][1]));
}

// ===========================================================================
// Edge kernel: persistent, 296 CTAs x 256 threads, 2 CTAs/SM.
// Tile = 64 edges x 128 outs, 8 warps = 2M x 4N, fp16 mma.
// Cross-tile double buffering: cp.async prefetch of tile t+1 overlaps
// compute of tile t; indices prefetched one further tile ahead.
// ===========================================================================
__global__ void __launch_bounds__(256, 2)
edge_mma_kernel(const int* __restrict__ rows,
                const int* __restrict__ cols,
                const float* __restrict__ bm1,
                const float* __restrict__ bm2)
{
    extern __shared__ char smem[];
    int*    sRowB = (int*)(smem + SM_ROW);     // [2][64]
    float*  sB1   = (float*)(smem + SM_B1);
    float*  sB2   = (float*)(smem + SM_B2);
    __half* sH    = (__half*)(smem + SM_H);

    const int tid  = threadIdx.x;
    const int lane = tid & 31;
    const int wid  = tid >> 5;
    const int wm   = wid & 1;
    const int wn   = wid >> 1;
    const uint32_t sb = smem_u32(smem);

    if (tid < 128) { sB1[tid] = __ldg(bm1 + tid); sB2[tid] = __ldg(bm2 + tid); }

    // gather mapping: each thread owns 128B of one edge row
    const int ge   = tid >> 2;
    const int gq   = tid & 3;
    const int ghalf = gq & 1;            // 0 = src node, 1 = dst node
    const int gseg  = gq >> 1;           // which 64-elem segment
    const uint32_t gDstOff = (uint32_t)((ge * LDA + ghalf * FDIM + gseg * 64) * 2);

    const int arow  = lane & 15;
    const int acolk = (lane >> 4) * 8;
    const int erow  = lane >> 2;
    const int ecol  = (lane & 3) * 2;

    const uint2* w1f = gW1f + wn * 4 * 32 + lane;
    const uint2* w2f = gW2f + wn * 4 * 32 + lane;

    const int stride = gridDim.x;
    int t = blockIdx.x;
    if (t >= N_TILES) return;

    // ---- prologue: gather tile t into buf 0, prefetch index for t+stride ----
    {
        int node = ghalf ? __ldg(cols + t * TILE_E + ge) : __ldg(rows + t * TILE_E + ge);
        if (tid < 16) cpa16(sb + SM_ROW + tid * 16, rows + t * TILE_E + tid * 4);
        const char* src = (const char*)(gF + (size_t)node * FDIM + gseg * 64);
        uint32_t dst = sb + SM_A + gDstOff;
        #pragma unroll
        for (int i = 0; i < 8; i++) cpa16(dst + i * 16, src + i * 16);
        CP_COMMIT();
    }
    int nodeAhead = 0;
    {
        int tn = t + stride;
        if (tn < N_TILES)
            nodeAhead = ghalf ? __ldg(cols + tn * TILE_E + ge) : __ldg(rows + tn * TILE_E + ge);
    }
    CP_WAIT0();
    __syncthreads();

    int cur = 0;
    for (;;) {
        const int t_next = t + stride;
        const bool haveNext = (t_next < N_TILES);

        // ---- issue prefetch of tile t+1 into buf cur^1 (no index stall) ----
        if (haveNext) {
            if (tid < 16) cpa16(sb + SM_ROW + (cur ^ 1) * 256 + tid * 16,
                                rows + t_next * TILE_E + tid * 4);
            const char* src = (const char*)(gF + (size_t)nodeAhead * FDIM + gseg * 64);
            uint32_t dst = sb + SM_A + (cur ^ 1) * ABUF + gDstOff;
            #pragma unroll
            for (int i = 0; i < 8; i++) cpa16(dst + i * 16, src + i * 16);
            CP_COMMIT();
            int t2 = t_next + stride;
            if (t2 < N_TILES)
                nodeAhead = ghalf ? __ldg(cols + t2 * TILE_E + ge)
                                  : __ldg(rows + t2 * TILE_E + ge);
        }

        const uint32_t aBase = sb + SM_A + cur * ABUF;
        const int* sRow = sRowB + cur * 64;

        // ---- GEMM1: [64,256] @ W1[256,128], fp16, B double-buffered ----
        float4 acc[2][4];
        #pragma unroll
        for (int m = 0; m < 2; m++)
            #pragma unroll
            for (int nf = 0; nf < 4; nf++) acc[m][nf] = make_float4(0.f, 0.f, 0.f, 0.f);

        uint2 bf[2][4];
        #pragma unroll
        for (int nf = 0; nf < 4; nf++) bf[0][nf] = __ldg(w1f + nf * 32);

        #pragma unroll 2
        for (int ks = 0; ks < 16; ks++) {
            const int c = ks & 1, nx = c ^ 1;
            uint32_t ah[2][4];
            #pragma unroll
            for (int m = 0; m < 2; m++) {
                uint32_t ab = aBase +
                    (uint32_t)(((wm * 32 + m * 16 + arow) * LDA + ks * 16 + acolk) * 2);
                ldmx4(ah[m], ab);
            }
            if (ks < 15) {
                #pragma unroll
                for (int nf = 0; nf < 4; nf++)
                    bf[nx][nf] = __ldg(w1f + ((ks + 1) * 16 + nf) * 32);
            }
            #pragma unroll
            for (int nf = 0; nf < 4; nf++)
                #pragma unroll
                for (int m = 0; m < 2; m++)
                    mma_f16(acc[m][nf], ah[m], bf[c][nf]);
        }

        // ---- epilogue 1: h = sigmoid(D1 + bm1) -> fp16 -> sH ----
        #pragma unroll
        for (int m = 0; m < 2; m++)
            #pragma unroll
            for (int nf = 0; nf < 4; nf++) {
                int r0 = wm * 32 + m * 16 + erow;
                int c  = wn * 32 + nf * 8 + ecol;
                float b0 = sB1[c], b1 = sB1[c + 1];
                *(uint32_t*)(sH + r0 * LDH + c) =
                    pack_h2(__float2half_rn(sigmoidf_(acc[m][nf].x + b0)),
                            __float2half_rn(sigmoidf_(acc[m][nf].y + b1)));
                *(uint32_t*)(sH + (r0 + 8) * LDH + c) =
                    pack_h2(__float2half_rn(sigmoidf_(acc[m][nf].z + b0)),
                            __float2half_rn(sigmoidf_(acc[m][nf].w + b1)));
            }
        __syncthreads();

        // ---- GEMM2: [64,128] @ W2[128,128], fp16 ----
        float4 acc2[2][4];
        #pragma unroll
        for (int m = 0; m < 2; m++)
            #pragma unroll
            for (int nf = 0; nf < 4; nf++) acc2[m][nf] = make_float4(0.f, 0.f, 0.f, 0.f);

        #pragma unroll
        for (int nf = 0; nf < 4; nf++) bf[0][nf] = __ldg(w2f + nf * 32);

        #pragma unroll 2
        for (int ks = 0; ks < 8; ks++) {
            const int c = ks & 1, nx = c ^ 1;
            uint32_t ah[2][4];
            #pragma unroll
            for (int m = 0; m < 2; m++) {
                uint32_t ab = sb + SM_H +
                    (uint32_t)(((wm * 32 + m * 16 + arow) * LDH + ks * 16 + acolk) * 2);
                ldmx4(ah[m], ab);
            }
            if (ks < 7) {
                #pragma unroll
                for (int nf = 0; nf < 4; nf++)
                    bf[nx][nf] = __ldg(w2f + ((ks + 1) * 16 + nf) * 32);
            }
            #pragma unroll
            for (int nf = 0; nf < 4; nf++)
                #pragma unroll
                for (int m = 0; m < 2; m++)
                    mma_f16(acc2[m][nf], ah[m], bf[c][nf]);
        }

        // ---- epilogue 2: softsign + red scatter into g_agg ----
        #pragma unroll
        for (int m = 0; m < 2; m++) {
            int r0 = wm * 32 + m * 16 + erow;
            int n0 = sRow[r0];
            int n1 = sRow[r0 + 8];
            #pragma unroll
            for (int nf = 0; nf < 4; nf++) {
                int c = wn * 32 + nf * 8 + ecol;
                float b0 = sB2[c], b1 = sB2[c + 1];
                red2(g_agg + (size_t)n0 * FDIM + c,
                     softsignf_(acc2[m][nf].x + b0), softsignf_(acc2[m][nf].y + b1));
                red2(g_agg + (size_t)n1 * FDIM + c,
                     softsignf_(acc2[m][nf].z + b0), softsignf_(acc2[m][nf].w + b1));
            }
        }

        if (!haveNext) break;
        CP_WAIT0();          // prefetch had the whole tile compute to land
        __syncthreads();     // next tile's A + sRow visible; sH reads done
        t = t_next;
        cur ^= 1;
    }
}

// ===========================================================================
// Node kernel (R7 version, unchanged)
// ===========================================================================
#define TEN 64
#define NLDH 132
#define NLDN 388

__global__ void __launch_bounds__(256, 2)
node_kernel(const float* __restrict__ features,
            const float* __restrict__ time_emb,
            const float* __restrict__ Wf1,
            const float* __restrict__ bf1,
            const float* __restrict__ Wf2,
            const float* __restrict__ bf2,
            float* __restrict__ out)
{
    extern __shared__ float smemf[];
    float* sIn = smemf;

    const int tid = threadIdx.x;
    const int tx  = tid & 31;
    const int ty  = tid >> 5;
    const int n0  = blockIdx.x * TEN;

    for (int n = ty; n < TEN; n += 8) {
        int node = n0 + n;
        float4 a, g, t;
        if (node < N_NODES) {
            a = __ldg((const float4*)(features + (size_t)node * FDIM) + tx);
            g = *((const float4*)(g_agg + (size_t)node * FDIM) + tx);
            t = __ldg((const float4*)(time_emb + (size_t)node * FDIM) + tx);
        } else {
            a = g = t = make_float4(0.f, 0.f, 0.f, 0.f);
        }
        *(float4*)&sIn[n * NLDN + tx * 4] =
            make_float4(sigmoidf_(a.x), sigmoidf_(a.y), sigmoidf_(a.z), sigmoidf_(a.w));
        *(float4*)&sIn[n * NLDN + FDIM + tx * 4] =
            make_float4(sigmoidf_(g.x), sigmoidf_(g.y), sigmoidf_(g.z), sigmoidf_(g.w));
        *(float4*)&sIn[n * NLDN + 2 * FDIM + tx * 4] =
            make_float4(sigmoidf_(t.x), sigmoidf_(t.y), sigmoidf_(t.z), sigmoidf_(t.w));
    }
    __syncthreads();

    u64 acc[8][2];
    #pragma unroll
    for (int e = 0; e < 8; e++) { acc[e][0] = 0ull; acc[e][1] = 0ull; }

    const float* wBase = Wf1 + tx * 4;
    const float* aBase = sIn + (ty * 8) * NLDN;

    #pragma unroll 2
    for (int k = 0; k < 3 * FDIM; k += 4) {
        u64 w0a, w0b, w1a, w1b, w2a, w2b, w3a, w3b;
        ldg2x2(wBase + (k + 0) * FDIM, w0a, w0b);
        ldg2x2(wBase + (k + 1) * FDIM, w1a, w1b);
        ldg2x2(wBase + (k + 2) * FDIM, w2a, w2b);
        ldg2x2(wBase + (k + 3) * FDIM, w3a, w3b);
        #pragma unroll
        for (int e = 0; e < 8; e++) {
            float4 a = *(const float4*)(aBase + e * NLDN + k);
            u64 a0 = pack2(a.x), a1 = pack2(a.y), a2 = pack2(a.z), a3 = pack2(a.w);
            ffma2(acc[e][0], a0, w0a); ffma2(acc[e][1], a0, w0b);
            ffma2(acc[e][0], a1, w1a); ffma2(acc[e][1], a1, w1b);
            ffma2(acc[e][0], a2, w2a); ffma2(acc[e][1], a2, w2b);
            ffma2(acc[e][0], a3, w3a); ffma2(acc[e][1], a3, w3b);
        }
    }
    __syncthreads();

    float4 b1 = __ldg((const float4*)bf1 + tx);
    float* sHf = smemf;
    #pragma unroll
    for (int e = 0; e < 8; e++) {
        float x0, x1, x2, x3;
        unpack2(acc[e][0], x0, x1);
        unpack2(acc[e][1], x2, x3);
        float4 h;
        h.x = sigmoidf_(x0 + b1.x);
        h.y = sigmoidf_(x1 + b1.y);
        h.z = sigmoidf_(x2 + b1.z);
        h.w = sigmoidf_(x3 + b1.w);
        *(float4*)&sHf[(ty * 8 + e) * NLDH + tx * 4] = h;
    }
    __syncthreads();

    u64 acc2[8][2];
    #pragma unroll
    for (int e = 0; e < 8; e++) { acc2[e][0] = 0ull; acc2[e][1] = 0ull; }

    const float* w2Base = Wf2 + tx * 4;
    const float* hBase  = sHf + (ty * 8) * NLDH;

    #pragma unroll 2
    for (int k = 0; k < FDIM; k += 4) {
        u64 w0a, w0b, w1a, w1b, w2a, w2b, w3a, w3b;
        ldg2x2(w2Base + (k + 0) * FDIM, w0a, w0b);
        ldg2x2(w2Base + (k + 1) * FDIM, w1a, w1b);
        ldg2x2(w2Base + (k + 2) * FDIM, w2a, w2b);
        ldg2x2(w2Base + (k + 3) * FDIM, w3a, w3b);
        #pragma unroll
        for (int e = 0; e < 8; e++) {
            float4 a = *(const float4*)(hBase + e * NLDH + k);
            u64 a0 = pack2(a.x), a1 = pack2(a.y), a2 = pack2(a.z), a3 = pack2(a.w);
            ffma2(acc2[e][0], a0, w0a); ffma2(acc2[e][1], a0, w0b);
            ffma2(acc2[e][0], a1, w1a); ffma2(acc2[e][1], a1, w1b);
            ffma2(acc2[e][0], a2, w2a); ffma2(acc2[e][1], a2, w2b);
            ffma2(acc2[e][0], a3, w3a); ffma2(acc2[e][1], a3, w3b);
        }
    }

    float4 b2 = __ldg((const float4*)bf2 + tx);
    #pragma unroll
    for (int e = 0; e < 8; e++) {
        int node = n0 + ty * 8 + e;
        if (node < N_NODES) {
            float x0, x1, x2, x3;
            unpack2(acc2[e][0], x0, x1);
            unpack2(acc2[e][1], x2, x3);
            float4 o;
            o.x = softsignf_(x0 + b2.x);
            o.y = softsignf_(x1 + b2.y);
            o.z = softsignf_(x2 + b2.z);
            o.w = softsignf_(x3 + b2.w);
            *(float4*)(out + (size_t)node * FDIM + tx * 4) = o;
        }
    }
}

// ===========================================================================
extern "C" void kernel_launch(void* const* d_in, const int* in_sizes, int n_in,
                              void* d_out, int out_size)
{
    const float* features = (const float*)d_in[0];
    const int*   rows     = (const int*)  d_in[1];
    const int*   cols     = (const int*)  d_in[2];
    const float* time_emb = (const float*)d_in[3];
    const float* Wm1      = (const float*)d_in[4];
    const float* bm1      = (const float*)d_in[5];
    const float* Wm2      = (const float*)d_in[6];
    const float* bm2      = (const float*)d_in[7];
    const float* Wf1      = (const float*)d_in[8];
    const float* bf1      = (const float*)d_in[9];
    const float* Wf2      = (const float*)d_in[10];
    const float* bf2      = (const float*)d_in[11];
    float* out = (float*)d_out;

    const int node_smem = TEN * NLDN * sizeof(float);
    cudaFuncSetAttribute(edge_mma_kernel, cudaFuncAttributeMaxDynamicSharedMemorySize, SM_TOTAL);
    cudaFuncSetAttribute(node_kernel,     cudaFuncAttributeMaxDynamicSharedMemorySize, node_smem);

    void* aggp = nullptr;
    cudaGetSymbolAddress(&aggp, g_agg);
    cudaMemsetAsync(aggp, 0, (size_t)N_NODES * FDIM * sizeof(float));

    uint2 *w1f, *w2f;
    cudaGetSymbolAddress((void**)&w1f, gW1f);
    cudaGetSymbolAddress((void**)&w2f, gW2f);

    prep_features<<<(N_NODES * FDIM + 255) / 256, 256>>>(features);
    prep_wfrag<<<32, 256>>>(Wm1, 16, w1f);
    prep_wfrag<<<16, 256>>>(Wm2,  8, w2f);

    edge_mma_kernel<<<296, 256, SM_TOTAL>>>(rows, cols, bm1, bm2);

    node_kernel<<<(N_NODES + TEN - 1) / TEN, 256, node_smem>>>(features, time_emb,
                                                               Wf1, bf1, Wf2, bf2, out);
}